// round 1
// baseline (speedup 1.0000x reference)
#include <cuda_runtime.h>
#include <math.h>

// ---------------- problem constants ----------------
#define BB   2
#define TT   2048
#define DM   512
#define NH   8
#define DH   64
#define DFF  2048
#define MM   (BB*TT)        // 4096 rows
#define CHK  64             // attention chunk
#define NC   (TT/CHK)       // 32 chunks
#define BH   (BB*NH)        // 16
#define STR  68             // padded smem stride for intra kernel

// ---------------- scratch (device globals; no allocs allowed) ----------------
__device__ float g_h   [MM*DM];
__device__ float g_q   [MM*DM];
__device__ float g_k   [MM*DM];
__device__ float g_v   [MM*DM];
__device__ float g_attn[MM*DM];
__device__ float g_x2  [MM*DM];
__device__ float g_h2  [MM*DM];
__device__ float g_ffn [MM*DFF];
__device__ float g_ckv [BH*NC*DH*DH];   // per-chunk K^T V sums
__device__ float g_cz  [BH*NC*DH];      // per-chunk K sums
__device__ float g_Sp  [BH*NC*DH*DH];   // exclusive-prefix states
__device__ float g_zp  [BH*NC*DH];      // exclusive-prefix z

// ---------------- layernorm: one block per row ----------------
__global__ __launch_bounds__(256) void ln_kernel(
    const float* __restrict__ x, const float* __restrict__ g,
    const float* __restrict__ b, float* __restrict__ o)
{
    int row = blockIdx.x;
    const float* xr = x + (size_t)row*DM;
    float* orow = o + (size_t)row*DM;
    int tid = threadIdx.x;
    float v0 = xr[tid], v1 = xr[tid+256];
    float s = v0+v1, s2 = v0*v0+v1*v1;
#pragma unroll
    for (int off=16; off; off>>=1){
        s  += __shfl_xor_sync(0xffffffffu, s,  off);
        s2 += __shfl_xor_sync(0xffffffffu, s2, off);
    }
    __shared__ float rs[8], rs2[8], mu_s, rstd_s;
    if ((tid&31)==0){ rs[tid>>5]=s; rs2[tid>>5]=s2; }
    __syncthreads();
    if (tid==0){
        float a=0.f,c=0.f;
#pragma unroll
        for (int i=0;i<8;i++){ a+=rs[i]; c+=rs2[i]; }
        float mu = a*(1.0f/DM);
        float var = c*(1.0f/DM) - mu*mu;
        mu_s = mu; rstd_s = rsqrtf(var + 1e-5f);
    }
    __syncthreads();
    float mu = mu_s, rstd = rstd_s;
    orow[tid]     = (v0-mu)*rstd*g[tid]     + b[tid];
    orow[tid+256] = (v1-mu)*rstd*g[tid+256] + b[tid+256];
}

// ---------------- SGEMM: C[M,N] = A[M,K] @ B[K,N] + bias, epilogue modes --------
// mode 0: +bias   1: elu(+bias)+1   2: +bias +res   3: relu(+bias)
#define GBM 128
#define GBN 128
#define GBK 8
__global__ __launch_bounds__(256) void gemm_kernel(
    const float* __restrict__ A, const float* __restrict__ Bm,
    const float* __restrict__ bias, const float* __restrict__ res,
    float* __restrict__ Cm, int Mdim, int Ndim, int Kdim, int mode)
{
    __shared__ float As[GBK][GBM];
    __shared__ float Bs[GBK][GBN];
    int tid = threadIdx.x;
    int bm = blockIdx.y * GBM;
    int bn = blockIdx.x * GBN;
    int tx = tid & 15, ty = tid >> 4;
    int m0 = ty*8, n0 = tx*8;
    float acc[8][8];
#pragma unroll
    for (int i=0;i<8;i++)
#pragma unroll
        for (int j=0;j<8;j++) acc[i][j]=0.f;

    int a_row = tid >> 1;
    int a_col = (tid & 1) * 4;
    int b_row = tid >> 5;
    int b_col = (tid & 31) * 4;
    const float* Ag = A + (size_t)(bm + a_row)*Kdim + a_col;
    const float* Bg = Bm + (size_t)b_row*Ndim + bn + b_col;

    for (int k0 = 0; k0 < Kdim; k0 += GBK) {
        float4 av = *(const float4*)(Ag + k0);
        float4 bv = *(const float4*)(Bg + (size_t)k0*Ndim);
        As[a_col+0][a_row]=av.x; As[a_col+1][a_row]=av.y;
        As[a_col+2][a_row]=av.z; As[a_col+3][a_row]=av.w;
        *(float4*)&Bs[b_row][b_col] = bv;
        __syncthreads();
#pragma unroll
        for (int kk=0; kk<GBK; kk++){
            float af[8], bf[8];
#pragma unroll
            for (int i=0;i<8;i++) af[i]=As[kk][m0+i];
#pragma unroll
            for (int j=0;j<8;j++) bf[j]=Bs[kk][n0+j];
#pragma unroll
            for (int i=0;i<8;i++)
#pragma unroll
                for (int j=0;j<8;j++)
                    acc[i][j] += af[i]*bf[j];
        }
        __syncthreads();
    }
#pragma unroll
    for (int i=0;i<8;i++){
        int m = bm+m0+i;
#pragma unroll
        for (int j=0;j<8;j++){
            int n = bn+n0+j;
            float v = acc[i][j] + bias[n];
            if (mode==1)       v = (v > 0.f) ? (v + 1.f) : expf(v);
            else if (mode==2)  v += res[(size_t)m*Ndim+n];
            else if (mode==3)  v = fmaxf(v, 0.f);
            Cm[(size_t)m*Ndim+n] = v;
        }
    }
}

// ---------------- per-chunk K^T V and K sums: block per (bh, chunk) -------------
__global__ __launch_bounds__(256) void chunk_sums_kernel(
    const float* __restrict__ Kf, const float* __restrict__ Vf,
    float* __restrict__ ckv, float* __restrict__ cz)
{
    __shared__ float Ks[CHK*DH];
    __shared__ float Vs[CHK*DH];
    int blk = blockIdx.x;
    int c = blk % NC, bh = blk / NC;
    int b = bh / NH, h = bh % NH;
    int t0 = c*CHK;
    int tid = threadIdx.x;
    int lr = tid >> 4;
    int lc = (tid & 15) * 4;
    for (int r = lr; r < CHK; r += 16){
        size_t gi = ((size_t)(b*TT + t0 + r))*DM + h*DH + lc;
        *(float4*)&Ks[r*DH+lc] = *(const float4*)(Kf+gi);
        *(float4*)&Vs[r*DH+lc] = *(const float4*)(Vf+gi);
    }
    __syncthreads();
    int ti = (tid>>4)*4, tj = (tid&15)*4;
    float acc[4][4];
#pragma unroll
    for (int i=0;i<4;i++)
#pragma unroll
        for (int j=0;j<4;j++) acc[i][j]=0.f;
    for (int t=0;t<CHK;t++){
        float4 kv = *(const float4*)&Ks[t*DH+ti];
        float4 vv = *(const float4*)&Vs[t*DH+tj];
        float kk[4]={kv.x,kv.y,kv.z,kv.w}, vf[4]={vv.x,vv.y,vv.z,vv.w};
#pragma unroll
        for (int i=0;i<4;i++)
#pragma unroll
            for (int j=0;j<4;j++) acc[i][j] += kk[i]*vf[j];
    }
    float* outp = ckv + (size_t)blk*DH*DH;
#pragma unroll
    for (int i=0;i<4;i++){
        float4 o = make_float4(acc[i][0],acc[i][1],acc[i][2],acc[i][3]);
        *(float4*)&outp[(ti+i)*DH + tj] = o;
    }
    if (tid < DH){
        float zsum = 0.f;
        for (int t=0;t<CHK;t++) zsum += Ks[t*DH+tid];
        cz[(size_t)blk*DH + tid] = zsum;
    }
}

// ---------------- exclusive scan over chunk states: block per (b,h) -------------
__global__ __launch_bounds__(256) void scan_kernel(
    const float* __restrict__ ckv, const float* __restrict__ cz,
    float* __restrict__ Sp, float* __restrict__ zp)
{
    int bh = blockIdx.x, tid = threadIdx.x;
    float s[16];
#pragma unroll
    for (int i=0;i<16;i++) s[i]=0.f;
    float z = 0.f;
    for (int c=0;c<NC;c++){
        size_t base = ((size_t)(bh*NC+c))*(DH*DH);
#pragma unroll
        for (int i=0;i<16;i++){
            size_t e = base + (size_t)i*256 + tid;
            Sp[e] = s[i];
            s[i] += ckv[e];
        }
        if (tid < DH){
            size_t ze = (size_t)(bh*NC+c)*DH + tid;
            zp[ze] = z;
            z += cz[ze];
        }
    }
}

// ---------------- intra-chunk attention: block per (bh, chunk) ------------------
__global__ __launch_bounds__(256) void intra_kernel(
    const float* __restrict__ Qf, const float* __restrict__ Kf,
    const float* __restrict__ Vf, const float* __restrict__ Sp,
    const float* __restrict__ zp, float* __restrict__ attn)
{
    extern __shared__ float sm[];
    float* Qt = sm;                 // [d][t] transposed
    float* Kt = Qt + 64*STR;        // [d][j] transposed
    float* Vs = Kt + 64*STR;        // [j][m]
    float* Ss = Vs + 64*STR;        // [d][m]
    float* At = Ss + 64*STR;        // [j][t] A transposed (masked)
    float* zs = At + 64*STR;        // 64
    float* dn = zs + 64;            // 64

    int blk = blockIdx.x;
    int c = blk % NC, bh = blk / NC;
    int b = bh / NH, h = bh % NH;
    int t0 = c*CHK;
    int tid = threadIdx.x;
    int lr = tid >> 4;
    int lc = (tid & 15) * 4;

    for (int r = lr; r < 64; r += 16){
        size_t gi = ((size_t)(b*TT + t0 + r))*DM + h*DH + lc;
        float4 q = *(const float4*)(Qf+gi);
        float4 k = *(const float4*)(Kf+gi);
        float4 v = *(const float4*)(Vf+gi);
        Qt[(lc+0)*STR+r]=q.x; Qt[(lc+1)*STR+r]=q.y; Qt[(lc+2)*STR+r]=q.z; Qt[(lc+3)*STR+r]=q.w;
        Kt[(lc+0)*STR+r]=k.x; Kt[(lc+1)*STR+r]=k.y; Kt[(lc+2)*STR+r]=k.z; Kt[(lc+3)*STR+r]=k.w;
        *(float4*)&Vs[r*STR+lc] = v;
    }
    {
        size_t base = (size_t)blk*(DH*DH);
        for (int e = tid*4; e < DH*DH; e += 1024){
            float4 sv = *(const float4*)(Sp + base + e);
            int d = e >> 6, m = e & 63;
            *(float4*)&Ss[d*STR+m] = sv;
        }
    }
    if (tid < DH) zs[tid] = zp[(size_t)blk*DH + tid];
    __syncthreads();

    int ti = (tid>>4)*4;   // row tile (t)
    int tj = (tid&15)*4;   // col tile (j / m)

    // A = Q K^T (causal-masked)
    float a[4][4];
#pragma unroll
    for (int i=0;i<4;i++)
#pragma unroll
        for (int j=0;j<4;j++) a[i][j]=0.f;
    for (int d=0; d<64; d++){
        float4 qv = *(const float4*)&Qt[d*STR+ti];
        float4 kv = *(const float4*)&Kt[d*STR+tj];
        float qq[4]={qv.x,qv.y,qv.z,qv.w}, kk[4]={kv.x,kv.y,kv.z,kv.w};
#pragma unroll
        for (int i=0;i<4;i++)
#pragma unroll
            for (int j=0;j<4;j++) a[i][j] += qq[i]*kk[j];
    }
#pragma unroll
    for (int i=0;i<4;i++)
#pragma unroll
        for (int j=0;j<4;j++)
            At[(tj+j)*STR + (ti+i)] = ((tj+j) <= (ti+i)) ? a[i][j] : 0.f;
    __syncthreads();

    // den per row
    if (tid < 64){
        int t = tid;
        float dsum = 0.f;
        for (int j=0;j<64;j++) dsum += At[j*STR + t];
        for (int d=0;d<64;d++) dsum += Qt[d*STR + t]*zs[d];
        dn[t] = fmaxf(dsum, 1e-6f);
    }
    __syncthreads();

    // num = A @ V + Q @ S_prev
    float nacc[4][4];
#pragma unroll
    for (int i=0;i<4;i++)
#pragma unroll
        for (int j=0;j<4;j++) nacc[i][j]=0.f;
    for (int j=0;j<64;j++){
        float4 av = *(const float4*)&At[j*STR+ti];
        float4 vv = *(const float4*)&Vs[j*STR+tj];
        float af[4]={av.x,av.y,av.z,av.w}, vf[4]={vv.x,vv.y,vv.z,vv.w};
#pragma unroll
        for (int i=0;i<4;i++)
#pragma unroll
            for (int m=0;m<4;m++) nacc[i][m] += af[i]*vf[m];
    }
    for (int d=0;d<64;d++){
        float4 qv = *(const float4*)&Qt[d*STR+ti];
        float4 sv = *(const float4*)&Ss[d*STR+tj];
        float qq[4]={qv.x,qv.y,qv.z,qv.w}, sf[4]={sv.x,sv.y,sv.z,sv.w};
#pragma unroll
        for (int i=0;i<4;i++)
#pragma unroll
            for (int m=0;m<4;m++) nacc[i][m] += qq[i]*sf[m];
    }
#pragma unroll
    for (int i=0;i<4;i++){
        float inv = 1.0f / dn[ti+i];
        float4 o = make_float4(nacc[i][0]*inv, nacc[i][1]*inv,
                               nacc[i][2]*inv, nacc[i][3]*inv);
        *(float4*)(attn + ((size_t)(b*TT + t0 + ti + i))*DM + h*DH + tj) = o;
    }
}

// ---------------- launch ----------------
#define SMEM_INTRA ((5*64*STR + 128) * sizeof(float))

extern "C" void kernel_launch(void* const* d_in, const int* in_sizes, int n_in,
                              void* d_out, int out_size)
{
    (void)in_sizes; (void)n_in; (void)out_size;
    const float* x     = (const float*)d_in[0];
    const float* ln1_g = (const float*)d_in[1];
    const float* ln1_b = (const float*)d_in[2];
    const float* Wq    = (const float*)d_in[3];
    const float* bq    = (const float*)d_in[4];
    const float* Wk    = (const float*)d_in[5];
    const float* bk    = (const float*)d_in[6];
    const float* Wv    = (const float*)d_in[7];
    const float* bv    = (const float*)d_in[8];
    const float* Wo    = (const float*)d_in[9];
    const float* bo    = (const float*)d_in[10];
    const float* ln2_g = (const float*)d_in[11];
    const float* ln2_b = (const float*)d_in[12];
    const float* W1    = (const float*)d_in[13];
    const float* b1    = (const float*)d_in[14];
    const float* W2    = (const float*)d_in[15];
    const float* b2    = (const float*)d_in[16];
    float* out = (float*)d_out;

    cudaFuncSetAttribute(intra_kernel, cudaFuncAttributeMaxDynamicSharedMemorySize,
                         (int)SMEM_INTRA);

    float *hb, *qb, *kb, *vb, *attnb, *x2b, *h2b, *ffnb, *ckvb, *czb, *Spb, *zpb;
    cudaGetSymbolAddress((void**)&hb,   g_h);
    cudaGetSymbolAddress((void**)&qb,   g_q);
    cudaGetSymbolAddress((void**)&kb,   g_k);
    cudaGetSymbolAddress((void**)&vb,   g_v);
    cudaGetSymbolAddress((void**)&attnb,g_attn);
    cudaGetSymbolAddress((void**)&x2b,  g_x2);
    cudaGetSymbolAddress((void**)&h2b,  g_h2);
    cudaGetSymbolAddress((void**)&ffnb, g_ffn);
    cudaGetSymbolAddress((void**)&ckvb, g_ckv);
    cudaGetSymbolAddress((void**)&czb,  g_cz);
    cudaGetSymbolAddress((void**)&Spb,  g_Sp);
    cudaGetSymbolAddress((void**)&zpb,  g_zp);

    dim3 gDM(DM/GBN, MM/GBM);     // (4, 32)
    dim3 gFF(DFF/GBN, MM/GBM);    // (16, 32)

    // sublayer 1
    ln_kernel<<<MM, 256>>>(x, ln1_g, ln1_b, hb);
    gemm_kernel<<<gDM, 256>>>(hb, Wq, bq, nullptr, qb, MM, DM, DM, 1);
    gemm_kernel<<<gDM, 256>>>(hb, Wk, bk, nullptr, kb, MM, DM, DM, 1);
    gemm_kernel<<<gDM, 256>>>(hb, Wv, bv, nullptr, vb, MM, DM, DM, 0);
    chunk_sums_kernel<<<BH*NC, 256>>>(kb, vb, ckvb, czb);
    scan_kernel<<<BH, 256>>>(ckvb, czb, Spb, zpb);
    intra_kernel<<<BH*NC, 256, SMEM_INTRA>>>(qb, kb, vb, Spb, zpb, attnb);
    gemm_kernel<<<gDM, 256>>>(attnb, Wo, bo, x, x2b, MM, DM, DM, 2);

    // sublayer 2
    ln_kernel<<<MM, 256>>>(x2b, ln2_g, ln2_b, h2b);
    gemm_kernel<<<gFF, 256>>>(h2b, W1, b1, nullptr, ffnb, MM, DFF, DM, 3);
    gemm_kernel<<<gDM, 256>>>(ffnb, W2, b2, x2b, out, MM, DM, DFF, 2);
}

// round 3
// speedup vs baseline: 2.5851x; 2.5851x over previous
#include <cuda_runtime.h>
#include <cuda_bf16.h>
#include <math.h>
#include <stdint.h>

// ---------------- problem constants ----------------
#define BB   2
#define TT   2048
#define DM   512
#define NH   8
#define DH   64
#define DFF  2048
#define MM   (BB*TT)        // 4096 rows
#define CHK  64
#define NC   (TT/CHK)       // 32
#define BH   (BB*NH)        // 16
#define STR  68
#define K3DM (3*DM)         // 1536
#define K3FF (3*DFF)        // 6144

// ---------------- scratch (device globals) ----------------
__device__ __align__(256) __nv_bfloat16 g_h3   [MM*K3DM];
__device__ __align__(256) float          g_q    [MM*DM];
__device__ __align__(256) float          g_k    [MM*DM];
__device__ __align__(256) float          g_v    [MM*DM];
__device__ __align__(256) __nv_bfloat16 g_attn3[MM*K3DM];
__device__ __align__(256) float          g_x2   [MM*DM];
__device__ __align__(256) __nv_bfloat16 g_h23  [MM*K3DM];
__device__ __align__(256) __nv_bfloat16 g_ffn3 [MM*K3FF];
__device__ __align__(256) __nv_bfloat16 g_wq3  [DM*K3DM];
__device__ __align__(256) __nv_bfloat16 g_wk3  [DM*K3DM];
__device__ __align__(256) __nv_bfloat16 g_wv3  [DM*K3DM];
__device__ __align__(256) __nv_bfloat16 g_wo3  [DM*K3DM];
__device__ __align__(256) __nv_bfloat16 g_w13  [DFF*K3DM];
__device__ __align__(256) __nv_bfloat16 g_w23  [DM*K3FF];
__device__ __align__(256) float g_ckv[BH*NC*DH*DH];
__device__ __align__(256) float g_cz [BH*NC*DH];
__device__ __align__(256) float g_Sp [BH*NC*DH*DH];
__device__ __align__(256) float g_zp [BH*NC*DH];

// ---------------- helpers ----------------
__device__ __forceinline__ uint32_t smem_u32(const void* p){
    uint32_t a;
    asm("{ .reg .u64 t; cvta.to.shared.u64 t, %1; cvt.u32.u64 %0, t; }"
        : "=r"(a) : "l"(p));
    return a;
}
__device__ __forceinline__ void cp16(uint32_t dst, const void* src){
    asm volatile("cp.async.cg.shared.global [%0], [%1], 16;" :: "r"(dst), "l"(src));
}
__device__ __forceinline__ void cp_commit(){
    asm volatile("cp.async.commit_group;");
}
template<int N> __device__ __forceinline__ void cp_wait(){
    asm volatile("cp.async.wait_group %0;" :: "n"(N));
}
__device__ __forceinline__ void bsplit(float v, __nv_bfloat16& h, __nv_bfloat16& l){
    h = __float2bfloat16(v);
    l = __float2bfloat16(v - __bfloat162float(h));
}
__device__ __forceinline__ void mma_bf16(float* d, const uint32_t* a, const uint32_t* b){
    asm volatile(
        "mma.sync.aligned.m16n8k16.row.col.f32.bf16.bf16.f32 "
        "{%0,%1,%2,%3}, {%4,%5,%6,%7}, {%8,%9}, {%0,%1,%2,%3};"
        : "+f"(d[0]), "+f"(d[1]), "+f"(d[2]), "+f"(d[3])
        : "r"(a[0]), "r"(a[1]), "r"(a[2]), "r"(a[3]), "r"(b[0]), "r"(b[1]));
}

// ---------------- layernorm -> triple-bf16 (A-side [hi,lo,hi]) ----------------
__global__ __launch_bounds__(256) void ln3_kernel(
    const float* __restrict__ x, const float* __restrict__ g,
    const float* __restrict__ b, __nv_bfloat16* __restrict__ o3)
{
    int row = blockIdx.x;
    const float* xr = x + (size_t)row*DM;
    int tid = threadIdx.x;
    float v0 = xr[tid], v1 = xr[tid+256];
    float s = v0+v1, s2 = v0*v0+v1*v1;
#pragma unroll
    for (int off=16; off; off>>=1){
        s  += __shfl_xor_sync(0xffffffffu, s,  off);
        s2 += __shfl_xor_sync(0xffffffffu, s2, off);
    }
    __shared__ float rs[8], rs2[8], mu_s, rstd_s;
    if ((tid&31)==0){ rs[tid>>5]=s; rs2[tid>>5]=s2; }
    __syncthreads();
    if (tid==0){
        float a=0.f,c=0.f;
#pragma unroll
        for (int i=0;i<8;i++){ a+=rs[i]; c+=rs2[i]; }
        float mu = a*(1.0f/DM);
        float var = c*(1.0f/DM) - mu*mu;
        mu_s = mu; rstd_s = rsqrtf(var + 1e-5f);
    }
    __syncthreads();
    float mu = mu_s, rstd = rstd_s;
    __nv_bfloat16* orow = o3 + (size_t)row*K3DM;
    {
        float y = (v0-mu)*rstd*g[tid] + b[tid];
        __nv_bfloat16 h,l; bsplit(y,h,l);
        orow[tid] = h; orow[tid+DM] = l; orow[tid+2*DM] = h;
    }
    {
        int c1 = tid+256;
        float y = (v1-mu)*rstd*g[c1] + b[c1];
        __nv_bfloat16 h,l; bsplit(y,h,l);
        orow[c1] = h; orow[c1+DM] = l; orow[c1+2*DM] = h;
    }
}

// ---------------- weight transpose+split: W[K,N] -> B'[N,3K] ([hi,hi,lo]) ------
__global__ __launch_bounds__(256) void wconv_kernel(
    const float* __restrict__ W, __nv_bfloat16* __restrict__ B3, int Kd, int Nd)
{
    __shared__ float t[32][33];
    int n0 = blockIdx.x*32, k0 = blockIdx.y*32;
    int tx = threadIdx.x, ty = threadIdx.y;
    for (int i=ty;i<32;i+=8)
        t[i][tx] = W[(size_t)(k0+i)*Nd + n0 + tx];
    __syncthreads();
    for (int i=ty;i<32;i+=8){
        float v = t[tx][i];
        __nv_bfloat16 h,l; bsplit(v,h,l);
        size_t base = (size_t)(n0+i)*(3*Kd) + k0 + tx;
        B3[base] = h; B3[base+Kd] = h; B3[base+2*Kd] = l;
    }
}

// ---------------- mma.sync bf16 GEMM: C[M,N] = A'[M,K'] @ B'[N,K']^T -----------
// tile 128x128, 8 warps (warp tile 32x64), K-chunk 64.
// modes: 0 +bias fp32; 1 elu(+bias)+1 fp32; 2 +bias+res fp32;
//        3 relu(+bias) -> triple bf16 (A-side) into C3.
#define TM 128
#define TN 128
#define KC 64
#define RS 72                       // padded smem row (elements)
#define ABYTES (TM*RS*2)            // 18432
#define SMEM_MM (4*ABYTES)          // A0,B0,A1,B1

__global__ __launch_bounds__(256) void mm_kernel(
    const __nv_bfloat16* __restrict__ Ap, const __nv_bfloat16* __restrict__ Bp,
    const float* __restrict__ bias, const float* __restrict__ res,
    float* __restrict__ Cf, __nv_bfloat16* __restrict__ C3,
    int Np, int Kp, int mode)
{
    extern __shared__ char smc[];
    uint32_t sb = smem_u32(smc);
    const uint32_t aoff[2] = { sb,            sb + 2*ABYTES };
    const uint32_t boff[2] = { sb + ABYTES,   sb + 3*ABYTES };

    int tid = threadIdx.x;
    int lane = tid & 31, wid = tid >> 5;
    int wm = wid >> 1, wn = wid & 1;
    int g = lane >> 2, qp = lane & 3;
    int bm = blockIdx.y * TM;
    int bn = blockIdx.x * TN;

    const char* Abase = (const char*)(Ap + (size_t)bm*Kp);
    const char* Bbase = (const char*)(Bp + (size_t)bn*Kp);
    const size_t rowb = (size_t)Kp*2;

    auto loadT = [&](const char* src, uint32_t dst, int c){
#pragma unroll
        for (int t=0;t<4;t++){
            int idx = tid + t*256;
            int r = idx >> 3, cc = idx & 7;
            cp16(dst + (uint32_t)(r*RS*2 + cc*16),
                 src + (size_t)r*rowb + c*128 + cc*16);
        }
    };

    float acc[2][8][4];
#pragma unroll
    for (int i=0;i<2;i++)
#pragma unroll
        for (int j=0;j<8;j++)
#pragma unroll
            for (int k=0;k<4;k++) acc[i][j][k]=0.f;

    const int nch = Kp >> 6;
    loadT(Abase, aoff[0], 0); loadT(Bbase, boff[0], 0); cp_commit();
    loadT(Abase, aoff[1], 1); loadT(Bbase, boff[1], 1); cp_commit();

    for (int i=0;i<nch;i++){
        int buf = i & 1;
        if (i+1 < nch) cp_wait<1>(); else cp_wait<0>();
        __syncthreads();
        uint32_t As = aoff[buf], Bs = boff[buf];
#pragma unroll
        for (int ks=0; ks<4; ks++){
            int kb = ks*16;
            uint32_t a[2][4];
#pragma unroll
            for (int mf=0; mf<2; mf++){
                int r = wm*32 + mf*16 + g;
                uint32_t base = As + (uint32_t)((r*RS + kb + qp*2)*2);
                asm volatile("ld.shared.b32 %0, [%1];"      : "=r"(a[mf][0]) : "r"(base));
                asm volatile("ld.shared.b32 %0, [%1+1152];" : "=r"(a[mf][1]) : "r"(base)); // +8 rows
                asm volatile("ld.shared.b32 %0, [%1+16];"   : "=r"(a[mf][2]) : "r"(base)); // +8 k
                asm volatile("ld.shared.b32 %0, [%1+1168];" : "=r"(a[mf][3]) : "r"(base));
            }
            uint32_t b[8][2];
#pragma unroll
            for (int nf=0; nf<8; nf++){
                int n = wn*64 + nf*8 + g;
                uint32_t base = Bs + (uint32_t)((n*RS + kb + qp*2)*2);
                asm volatile("ld.shared.b32 %0, [%1];"    : "=r"(b[nf][0]) : "r"(base));
                asm volatile("ld.shared.b32 %0, [%1+16];" : "=r"(b[nf][1]) : "r"(base));
            }
#pragma unroll
            for (int mf=0; mf<2; mf++)
#pragma unroll
                for (int nf=0; nf<8; nf++)
                    mma_bf16(acc[mf][nf], a[mf], b[nf]);
        }
        __syncthreads();
        if (i+2 < nch){
            loadT(Abase, aoff[buf], i+2);
            loadT(Bbase, boff[buf], i+2);
            cp_commit();
        }
    }

    // ---- epilogue ----
#pragma unroll
    for (int mf=0; mf<2; mf++){
#pragma unroll
        for (int half=0; half<2; half++){
            int m = bm + wm*32 + mf*16 + g + half*8;
#pragma unroll
            for (int nf=0; nf<8; nf++){
                int n = bn + wn*64 + nf*8 + qp*2;
                float v0 = acc[mf][nf][half*2+0] + bias[n];
                float v1 = acc[mf][nf][half*2+1] + bias[n+1];
                if (mode==1){
                    v0 = (v0 > 0.f) ? (v0+1.f) : expf(v0);
                    v1 = (v1 > 0.f) ? (v1+1.f) : expf(v1);
                } else if (mode==3){
                    v0 = fmaxf(v0, 0.f); v1 = fmaxf(v1, 0.f);
                } else if (mode==2){
                    float2 rr = *(const float2*)&res[(size_t)m*Np + n];
                    v0 += rr.x; v1 += rr.y;
                }
                if (mode==3){
                    __nv_bfloat16 h0,l0,h1,l1;
                    bsplit(v0,h0,l0); bsplit(v1,h1,l1);
                    uint32_t hw = ((uint32_t)__bfloat16_as_ushort(h1)<<16) | __bfloat16_as_ushort(h0);
                    uint32_t lw = ((uint32_t)__bfloat16_as_ushort(l1)<<16) | __bfloat16_as_ushort(l0);
                    __nv_bfloat16* p0 = C3 + (size_t)m*3*Np + n;
                    *(uint32_t*)(p0)        = hw;
                    *(uint32_t*)(p0 + Np)   = lw;
                    *(uint32_t*)(p0 + 2*Np) = hw;
                } else {
                    *(float2*)&Cf[(size_t)m*Np + n] = make_float2(v0, v1);
                }
            }
        }
    }
}

// ---------------- per-chunk K^T V and K sums ----------------
__global__ __launch_bounds__(256) void chunk_sums_kernel(
    const float* __restrict__ Kf, const float* __restrict__ Vf,
    float* __restrict__ ckv, float* __restrict__ cz)
{
    __shared__ float Ks[CHK*DH];
    __shared__ float Vs[CHK*DH];
    int blk = blockIdx.x;
    int c = blk % NC, bh = blk / NC;
    int b = bh / NH, h = bh % NH;
    int t0 = c*CHK;
    int tid = threadIdx.x;
    int lr = tid >> 4;
    int lc = (tid & 15) * 4;
    for (int r = lr; r < CHK; r += 16){
        size_t gi = ((size_t)(b*TT + t0 + r))*DM + h*DH + lc;
        *(float4*)&Ks[r*DH+lc] = *(const float4*)(Kf+gi);
        *(float4*)&Vs[r*DH+lc] = *(const float4*)(Vf+gi);
    }
    __syncthreads();
    int ti = (tid>>4)*4, tj = (tid&15)*4;
    float acc[4][4];
#pragma unroll
    for (int i=0;i<4;i++)
#pragma unroll
        for (int j=0;j<4;j++) acc[i][j]=0.f;
    for (int t=0;t<CHK;t++){
        float4 kv = *(const float4*)&Ks[t*DH+ti];
        float4 vv = *(const float4*)&Vs[t*DH+tj];
        float kk[4]={kv.x,kv.y,kv.z,kv.w}, vf[4]={vv.x,vv.y,vv.z,vv.w};
#pragma unroll
        for (int i=0;i<4;i++)
#pragma unroll
            for (int j=0;j<4;j++) acc[i][j] += kk[i]*vf[j];
    }
    float* outp = ckv + (size_t)blk*DH*DH;
#pragma unroll
    for (int i=0;i<4;i++)
        *(float4*)&outp[(ti+i)*DH + tj] =
            make_float4(acc[i][0],acc[i][1],acc[i][2],acc[i][3]);
    if (tid < DH){
        float zsum = 0.f;
        for (int t=0;t<CHK;t++) zsum += Ks[t*DH+tid];
        cz[(size_t)blk*DH + tid] = zsum;
    }
}

// ---------------- exclusive scan over chunk states ----------------
__global__ __launch_bounds__(256) void scan_kernel(
    const float* __restrict__ ckv, const float* __restrict__ cz,
    float* __restrict__ Sp, float* __restrict__ zp)
{
    int bh = blockIdx.x, tid = threadIdx.x;
    float s[16];
#pragma unroll
    for (int i=0;i<16;i++) s[i]=0.f;
    float z = 0.f;
    for (int c=0;c<NC;c++){
        size_t base = ((size_t)(bh*NC+c))*(DH*DH);
#pragma unroll
        for (int i=0;i<16;i++){
            size_t e = base + (size_t)i*256 + tid;
            Sp[e] = s[i];
            s[i] += ckv[e];
        }
        if (tid < DH){
            size_t ze = (size_t)(bh*NC+c)*DH + tid;
            zp[ze] = z;
            z += cz[ze];
        }
    }
}

// ---------------- intra-chunk attention -> triple bf16 output ----------------
__global__ __launch_bounds__(256) void intra_kernel(
    const float* __restrict__ Qf, const float* __restrict__ Kf,
    const float* __restrict__ Vf, const float* __restrict__ Sp,
    const float* __restrict__ zp, __nv_bfloat16* __restrict__ attn3)
{
    extern __shared__ float smf[];
    float* Qt = smf;
    float* Kt = Qt + 64*STR;
    float* Vs = Kt + 64*STR;
    float* Ss = Vs + 64*STR;
    float* At = Ss + 64*STR;
    float* zs = At + 64*STR;
    float* dn = zs + 64;

    int blk = blockIdx.x;
    int c = blk % NC, bh = blk / NC;
    int b = bh / NH, h = bh % NH;
    int t0 = c*CHK;
    int tid = threadIdx.x;
    int lr = tid >> 4;
    int lc = (tid & 15) * 4;

    for (int r = lr; r < 64; r += 16){
        size_t gi = ((size_t)(b*TT + t0 + r))*DM + h*DH + lc;
        float4 q = *(const float4*)(Qf+gi);
        float4 k = *(const float4*)(Kf+gi);
        float4 v = *(const float4*)(Vf+gi);
        Qt[(lc+0)*STR+r]=q.x; Qt[(lc+1)*STR+r]=q.y; Qt[(lc+2)*STR+r]=q.z; Qt[(lc+3)*STR+r]=q.w;
        Kt[(lc+0)*STR+r]=k.x; Kt[(lc+1)*STR+r]=k.y; Kt[(lc+2)*STR+r]=k.z; Kt[(lc+3)*STR+r]=k.w;
        *(float4*)&Vs[r*STR+lc] = v;
    }
    {
        size_t base = (size_t)blk*(DH*DH);
        for (int e = tid*4; e < DH*DH; e += 1024){
            float4 sv = *(const float4*)(Sp + base + e);
            int d = e >> 6, m = e & 63;
            *(float4*)&Ss[d*STR+m] = sv;
        }
    }
    if (tid < DH) zs[tid] = zp[(size_t)blk*DH + tid];
    __syncthreads();

    int ti = (tid>>4)*4;
    int tj = (tid&15)*4;

    float a[4][4];
#pragma unroll
    for (int i=0;i<4;i++)
#pragma unroll
        for (int j=0;j<4;j++) a[i][j]=0.f;
    for (int d=0; d<64; d++){
        float4 qv = *(const float4*)&Qt[d*STR+ti];
        float4 kv = *(const float4*)&Kt[d*STR+tj];
        float qq[4]={qv.x,qv.y,qv.z,qv.w}, kk[4]={kv.x,kv.y,kv.z,kv.w};
#pragma unroll
        for (int i=0;i<4;i++)
#pragma unroll
            for (int j=0;j<4;j++) a[i][j] += qq[i]*kk[j];
    }
#pragma unroll
    for (int i=0;i<4;i++)
#pragma unroll
        for (int j=0;j<4;j++)
            At[(tj+j)*STR + (ti+i)] = ((tj+j) <= (ti+i)) ? a[i][j] : 0.f;
    __syncthreads();

    if (tid < 64){
        int t = tid;
        float dsum = 0.f;
        for (int j=0;j<64;j++) dsum += At[j*STR + t];
        for (int d=0;d<64;d++) dsum += Qt[d*STR + t]*zs[d];
        dn[t] = fmaxf(dsum, 1e-6f);
    }
    __syncthreads();

    float nacc[4][4];
#pragma unroll
    for (int i=0;i<4;i++)
#pragma unroll
        for (int j=0;j<4;j++) nacc[i][j]=0.f;
    for (int j=0;j<64;j++){
        float4 av = *(const float4*)&At[j*STR+ti];
        float4 vv = *(const float4*)&Vs[j*STR+tj];
        float af[4]={av.x,av.y,av.z,av.w}, vf[4]={vv.x,vv.y,vv.z,vv.w};
#pragma unroll
        for (int i=0;i<4;i++)
#pragma unroll
            for (int m=0;m<4;m++) nacc[i][m] += af[i]*vf[m];
    }
    for (int d=0;d<64;d++){
        float4 qv = *(const float4*)&Qt[d*STR+ti];
        float4 sv = *(const float4*)&Ss[d*STR+tj];
        float qq[4]={qv.x,qv.y,qv.z,qv.w}, sf[4]={sv.x,sv.y,sv.z,sv.w};
#pragma unroll
        for (int i=0;i<4;i++)
#pragma unroll
            for (int m=0;m<4;m++) nacc[i][m] += qq[i]*sf[m];
    }
#pragma unroll
    for (int i=0;i<4;i++){
        float inv = 1.0f / dn[ti+i];
        size_t gm = (size_t)(b*TT + t0 + ti + i);
        __nv_bfloat16* p = attn3 + gm*K3DM + h*DH + tj;
        uint32_t hw[2], lw[2];
#pragma unroll
        for (int q=0;q<2;q++){
            float a0 = nacc[i][2*q]*inv, a1 = nacc[i][2*q+1]*inv;
            __nv_bfloat16 h0,l0,h1,l1;
            bsplit(a0,h0,l0); bsplit(a1,h1,l1);
            hw[q] = ((uint32_t)__bfloat16_as_ushort(h1)<<16) | __bfloat16_as_ushort(h0);
            lw[q] = ((uint32_t)__bfloat16_as_ushort(l1)<<16) | __bfloat16_as_ushort(l0);
        }
        *(uint2*)(p)        = make_uint2(hw[0],hw[1]);
        *(uint2*)(p+DM)     = make_uint2(lw[0],lw[1]);
        *(uint2*)(p+2*DM)   = make_uint2(hw[0],hw[1]);
    }
}

// ---------------- launch ----------------
#define SMEM_INTRA ((5*64*STR + 128) * sizeof(float))

extern "C" void kernel_launch(void* const* d_in, const int* in_sizes, int n_in,
                              void* d_out, int out_size)
{
    (void)in_sizes; (void)n_in; (void)out_size;
    const float* x     = (const float*)d_in[0];
    const float* ln1_g = (const float*)d_in[1];
    const float* ln1_b = (const float*)d_in[2];
    const float* Wq    = (const float*)d_in[3];
    const float* bq    = (const float*)d_in[4];
    const float* Wk    = (const float*)d_in[5];
    const float* bk    = (const float*)d_in[6];
    const float* Wv    = (const float*)d_in[7];
    const float* bv    = (const float*)d_in[8];
    const float* Wo    = (const float*)d_in[9];
    const float* bo    = (const float*)d_in[10];
    const float* ln2_g = (const float*)d_in[11];
    const float* ln2_b = (const float*)d_in[12];
    const float* W1    = (const float*)d_in[13];
    const float* b1    = (const float*)d_in[14];
    const float* W2    = (const float*)d_in[15];
    const float* b2    = (const float*)d_in[16];
    float* out = (float*)d_out;

    static bool attr_done = false;
    if (!attr_done){
        cudaFuncSetAttribute(intra_kernel, cudaFuncAttributeMaxDynamicSharedMemorySize,
                             (int)SMEM_INTRA);
        cudaFuncSetAttribute(mm_kernel, cudaFuncAttributeMaxDynamicSharedMemorySize,
                             SMEM_MM);
        attr_done = true;
    }

    __nv_bfloat16 *h3b,*attn3b,*h23b,*ffn3b,*wq3,*wk3,*wv3,*wo3,*w13,*w23;
    float *qb,*kb,*vb,*x2b,*ckvb,*czb,*Spb,*zpb;
    cudaGetSymbolAddress((void**)&h3b,   g_h3);
    cudaGetSymbolAddress((void**)&qb,    g_q);
    cudaGetSymbolAddress((void**)&kb,    g_k);
    cudaGetSymbolAddress((void**)&vb,    g_v);
    cudaGetSymbolAddress((void**)&attn3b,g_attn3);
    cudaGetSymbolAddress((void**)&x2b,   g_x2);
    cudaGetSymbolAddress((void**)&h23b,  g_h23);
    cudaGetSymbolAddress((void**)&ffn3b, g_ffn3);
    cudaGetSymbolAddress((void**)&wq3,   g_wq3);
    cudaGetSymbolAddress((void**)&wk3,   g_wk3);
    cudaGetSymbolAddress((void**)&wv3,   g_wv3);
    cudaGetSymbolAddress((void**)&wo3,   g_wo3);
    cudaGetSymbolAddress((void**)&w13,   g_w13);
    cudaGetSymbolAddress((void**)&w23,   g_w23);
    cudaGetSymbolAddress((void**)&ckvb,  g_ckv);
    cudaGetSymbolAddress((void**)&czb,   g_cz);
    cudaGetSymbolAddress((void**)&Spb,   g_Sp);
    cudaGetSymbolAddress((void**)&zpb,   g_zp);

    dim3 wc_small(DM/32, DM/32);
    dim3 wc_w1(DFF/32, DM/32);
    dim3 wc_w2(DM/32, DFF/32);
    dim3 wcb(32,8);

    wconv_kernel<<<wc_small, wcb>>>(Wq, wq3, DM, DM);
    wconv_kernel<<<wc_small, wcb>>>(Wk, wk3, DM, DM);
    wconv_kernel<<<wc_small, wcb>>>(Wv, wv3, DM, DM);
    wconv_kernel<<<wc_small, wcb>>>(Wo, wo3, DM, DM);
    wconv_kernel<<<wc_w1, wcb>>>(W1, w13, DM, DFF);
    wconv_kernel<<<wc_w2, wcb>>>(W2, w23, DFF, DM);

    dim3 gDM(DM/TN, MM/TM);         // (4, 32)
    dim3 gFF(DFF/TN, MM/TM);        // (16, 32)

    // sublayer 1
    ln3_kernel<<<MM, 256>>>(x, ln1_g, ln1_b, h3b);
    mm_kernel<<<gDM, 256, SMEM_MM>>>(h3b, wq3, bq, nullptr, qb, nullptr, DM, K3DM, 1);
    mm_kernel<<<gDM, 256, SMEM_MM>>>(h3b, wk3, bk, nullptr, kb, nullptr, DM, K3DM, 1);
    mm_kernel<<<gDM, 256, SMEM_MM>>>(h3b, wv3, bv, nullptr, vb, nullptr, DM, K3DM, 0);
    chunk_sums_kernel<<<BH*NC, 256>>>(kb, vb, ckvb, czb);
    scan_kernel<<<BH, 256>>>(ckvb, czb, Spb, zpb);
    intra_kernel<<<BH*NC, 256, SMEM_INTRA>>>(qb, kb, vb, Spb, zpb, attn3b);
    mm_kernel<<<gDM, 256, SMEM_MM>>>(attn3b, wo3, bo, x, x2b, nullptr, DM, K3DM, 2);

    // sublayer 2
    ln3_kernel<<<MM, 256>>>(x2b, ln2_g, ln2_b, h23b);
    mm_kernel<<<gFF, 256, SMEM_MM>>>(h23b, w13, b1, nullptr, nullptr, ffn3b, DFF, K3DM, 3);
    mm_kernel<<<gDM, 256, SMEM_MM>>>(ffn3b, w23, b2, x2b, out, nullptr, DM, K3FF, 2);
}

// round 4
// speedup vs baseline: 2.6837x; 1.0382x over previous
#include <cuda_runtime.h>
#include <cuda_bf16.h>
#include <math.h>
#include <stdint.h>

// ---------------- problem constants ----------------
#define BB   2
#define TT   2048
#define DM   512
#define NH   8
#define DH   64
#define DFF  2048
#define MM   (BB*TT)        // 4096 rows
#define CHK  64
#define NC   (TT/CHK)       // 32
#define BH   (BB*NH)        // 16
#define STR  68
#define K3DM (3*DM)         // 1536
#define K3FF (3*DFF)        // 6144

// ---------------- scratch (device globals) ----------------
__device__ __align__(256) __nv_bfloat16 g_h3   [MM*K3DM];
__device__ __align__(256) float          g_q    [MM*DM];
__device__ __align__(256) float          g_k    [MM*DM];
__device__ __align__(256) float          g_v    [MM*DM];
__device__ __align__(256) __nv_bfloat16 g_attn3[MM*K3DM];
__device__ __align__(256) float          g_x2   [MM*DM];
__device__ __align__(256) __nv_bfloat16 g_h23  [MM*K3DM];
__device__ __align__(256) __nv_bfloat16 g_ffn3 [MM*K3FF];
__device__ __align__(256) __nv_bfloat16 g_wqkv3[3*DM*K3DM];   // rows: [Wq|Wk|Wv]
__device__ __align__(256) __nv_bfloat16 g_wo3  [DM*K3DM];
__device__ __align__(256) __nv_bfloat16 g_w13  [DFF*K3DM];
__device__ __align__(256) __nv_bfloat16 g_w23  [DM*K3FF];
__device__ __align__(256) float g_ckv[BH*NC*DH*DH];
__device__ __align__(256) float g_cz [BH*NC*DH];
__device__ __align__(256) float g_Sp [BH*NC*DH*DH];
__device__ __align__(256) float g_zp [BH*NC*DH];

// ---------------- helpers ----------------
__device__ __forceinline__ uint32_t smem_u32(const void* p){
    uint32_t a;
    asm("{ .reg .u64 t; cvta.to.shared.u64 t, %1; cvt.u32.u64 %0, t; }"
        : "=r"(a) : "l"(p));
    return a;
}
__device__ __forceinline__ void cp16(uint32_t dst, const void* src){
    asm volatile("cp.async.cg.shared.global [%0], [%1], 16;" :: "r"(dst), "l"(src));
}
__device__ __forceinline__ void cp_commit(){
    asm volatile("cp.async.commit_group;");
}
template<int N> __device__ __forceinline__ void cp_wait(){
    asm volatile("cp.async.wait_group %0;" :: "n"(N));
}
__device__ __forceinline__ void bsplit(float v, __nv_bfloat16& h, __nv_bfloat16& l){
    h = __float2bfloat16(v);
    l = __float2bfloat16(v - __bfloat162float(h));
}
__device__ __forceinline__ void mma_bf16(float* d, const uint32_t* a, const uint32_t* b){
    asm volatile(
        "mma.sync.aligned.m16n8k16.row.col.f32.bf16.bf16.f32 "
        "{%0,%1,%2,%3}, {%4,%5,%6,%7}, {%8,%9}, {%0,%1,%2,%3};"
        : "+f"(d[0]), "+f"(d[1]), "+f"(d[2]), "+f"(d[3])
        : "r"(a[0]), "r"(a[1]), "r"(a[2]), "r"(a[3]), "r"(b[0]), "r"(b[1]));
}
__device__ __forceinline__ void ldsm4(uint32_t& r0, uint32_t& r1, uint32_t& r2,
                                      uint32_t& r3, uint32_t addr){
    asm volatile("ldmatrix.sync.aligned.m8n8.x4.shared.b16 {%0,%1,%2,%3}, [%4];"
                 : "=r"(r0), "=r"(r1), "=r"(r2), "=r"(r3) : "r"(addr));
}

// ---------------- layernorm -> triple-bf16 (A-side [hi,lo,hi]) ----------------
__global__ __launch_bounds__(256) void ln3_kernel(
    const float* __restrict__ x, const float* __restrict__ g,
    const float* __restrict__ b, __nv_bfloat16* __restrict__ o3)
{
    int row = blockIdx.x;
    const float* xr = x + (size_t)row*DM;
    int tid = threadIdx.x;
    float v0 = xr[tid], v1 = xr[tid+256];
    float s = v0+v1, s2 = v0*v0+v1*v1;
#pragma unroll
    for (int off=16; off; off>>=1){
        s  += __shfl_xor_sync(0xffffffffu, s,  off);
        s2 += __shfl_xor_sync(0xffffffffu, s2, off);
    }
    __shared__ float rs[8], rs2[8], mu_s, rstd_s;
    if ((tid&31)==0){ rs[tid>>5]=s; rs2[tid>>5]=s2; }
    __syncthreads();
    if (tid==0){
        float a=0.f,c=0.f;
#pragma unroll
        for (int i=0;i<8;i++){ a+=rs[i]; c+=rs2[i]; }
        float mu = a*(1.0f/DM);
        float var = c*(1.0f/DM) - mu*mu;
        mu_s = mu; rstd_s = rsqrtf(var + 1e-5f);
    }
    __syncthreads();
    float mu = mu_s, rstd = rstd_s;
    __nv_bfloat16* orow = o3 + (size_t)row*K3DM;
    {
        float y = (v0-mu)*rstd*g[tid] + b[tid];
        __nv_bfloat16 h,l; bsplit(y,h,l);
        orow[tid] = h; orow[tid+DM] = l; orow[tid+2*DM] = h;
    }
    {
        int c1 = tid+256;
        float y = (v1-mu)*rstd*g[c1] + b[c1];
        __nv_bfloat16 h,l; bsplit(y,h,l);
        orow[c1] = h; orow[c1+DM] = l; orow[c1+2*DM] = h;
    }
}

// -------- weight transpose+split: W[K,N] -> B'[N,3K] ([hi,hi,lo]), vectorized ----
// grid (Nd/32, Kd/64), block (32,8)
__global__ __launch_bounds__(256) void wconv_kernel(
    const float* __restrict__ W, __nv_bfloat16* __restrict__ B3, int Kd, int Nd)
{
    __shared__ float t[64][33];
    int n0 = blockIdx.x*32, k0 = blockIdx.y*64;
    int tx = threadIdx.x, ty = threadIdx.y;
#pragma unroll
    for (int i=ty;i<64;i+=8)
        t[i][tx] = W[(size_t)(k0+i)*Nd + n0 + tx];
    __syncthreads();
#pragma unroll
    for (int i=ty;i<32;i+=8){
        float va = t[2*tx][i], vb = t[2*tx+1][i];
        __nv_bfloat16 ha,la,hb,lb;
        bsplit(va,ha,la); bsplit(vb,hb,lb);
        uint32_t hw = ((uint32_t)__bfloat16_as_ushort(hb)<<16) | __bfloat16_as_ushort(ha);
        uint32_t lw = ((uint32_t)__bfloat16_as_ushort(lb)<<16) | __bfloat16_as_ushort(la);
        size_t base = (size_t)(n0+i)*(3*Kd) + k0 + 2*tx;
        *(uint32_t*)&B3[base]        = hw;
        *(uint32_t*)&B3[base+Kd]     = hw;
        *(uint32_t*)&B3[base+2*Kd]   = lw;
    }
}

// ---------------- mma.sync bf16 GEMM with ldmatrix ----------------
// tile 128x128, 8 warps (warp tile 32x64), K-chunk 64.
// modes: 0 +bias0 -> C0; 2 +bias0+res -> C0; 3 relu(+bias0) -> triple bf16 C3;
//        4 qkv split: n<512 -> C0(elu+1,bias0), <1024 -> C1(elu+1,bias1), else C2(bias2)
#define TM 128
#define TN 128
#define RS 72                       // padded smem row (elements)
#define ABYTES (TM*RS*2)            // 18432
#define SMEM_MM (4*ABYTES)          // A0,B0,A1,B1

__global__ __launch_bounds__(256) void mm_kernel(
    const __nv_bfloat16* __restrict__ Ap, const __nv_bfloat16* __restrict__ Bp,
    const float* __restrict__ bias0, const float* __restrict__ bias1,
    const float* __restrict__ bias2, const float* __restrict__ res,
    float* __restrict__ C0, float* __restrict__ C1, float* __restrict__ C2,
    __nv_bfloat16* __restrict__ C3,
    int Np, int Kp, int mode)
{
    extern __shared__ char smc[];
    uint32_t sb = smem_u32(smc);
    const uint32_t aoff[2] = { sb,            sb + 2*ABYTES };
    const uint32_t boff[2] = { sb + ABYTES,   sb + 3*ABYTES };

    int tid = threadIdx.x;
    int lane = tid & 31, wid = tid >> 5;
    int wm = wid >> 1, wn = wid & 1;
    int g = lane >> 2, qp = lane & 3;
    int bm = blockIdx.y * TM;
    int bn = blockIdx.x * TN;

    const char* Abase = (const char*)(Ap + (size_t)bm*Kp);
    const char* Bbase = (const char*)(Bp + (size_t)bn*Kp);
    const size_t rowb = (size_t)Kp*2;

    auto loadT = [&](const char* src, uint32_t dst, int c){
#pragma unroll
        for (int t=0;t<4;t++){
            int idx = tid + t*256;
            int r = idx >> 3, cc = idx & 7;
            cp16(dst + (uint32_t)(r*RS*2 + cc*16),
                 src + (size_t)r*rowb + c*128 + cc*16);
        }
    };

    // per-lane ldmatrix base offsets (within a buffer)
    uint32_t a_off[2], b_off[4];
#pragma unroll
    for (int mf=0; mf<2; mf++){
        int arow = wm*32 + mf*16 + (lane & 15);
        a_off[mf] = (uint32_t)(arow*(RS*2) + ((lane & 16) ? 16 : 0));
    }
#pragma unroll
    for (int p=0; p<4; p++){
        int nrow = wn*64 + p*16 + (lane & 7) + ((lane & 16) >> 1);
        b_off[p] = (uint32_t)(nrow*(RS*2) + ((lane & 8) ? 16 : 0));
    }

    float acc[2][8][4];
#pragma unroll
    for (int i=0;i<2;i++)
#pragma unroll
        for (int j=0;j<8;j++)
#pragma unroll
            for (int k=0;k<4;k++) acc[i][j][k]=0.f;

    const int nch = Kp >> 6;
    loadT(Abase, aoff[0], 0); loadT(Bbase, boff[0], 0); cp_commit();
    loadT(Abase, aoff[1], 1); loadT(Bbase, boff[1], 1); cp_commit();

    for (int i=0;i<nch;i++){
        int buf = i & 1;
        if (i+1 < nch) cp_wait<1>(); else cp_wait<0>();
        __syncthreads();
        uint32_t As = aoff[buf], Bs = boff[buf];
#pragma unroll
        for (int ks=0; ks<4; ks++){
            uint32_t koff = (uint32_t)(ks*32);
            uint32_t a[2][4];
            ldsm4(a[0][0],a[0][1],a[0][2],a[0][3], As + a_off[0] + koff);
            ldsm4(a[1][0],a[1][1],a[1][2],a[1][3], As + a_off[1] + koff);
            uint32_t b[8][2];
#pragma unroll
            for (int p=0; p<4; p++)
                ldsm4(b[2*p][0],b[2*p][1],b[2*p+1][0],b[2*p+1][1],
                      Bs + b_off[p] + koff);
#pragma unroll
            for (int mf=0; mf<2; mf++)
#pragma unroll
                for (int nf=0; nf<8; nf++)
                    mma_bf16(acc[mf][nf], a[mf], b[nf]);
        }
        __syncthreads();
        if (i+2 < nch){
            loadT(Abase, aoff[buf], i+2);
            loadT(Bbase, boff[buf], i+2);
            cp_commit();
        }
    }

    // ---- epilogue ----
#pragma unroll
    for (int mf=0; mf<2; mf++){
#pragma unroll
        for (int half=0; half<2; half++){
            int m = bm + wm*32 + mf*16 + g + half*8;
#pragma unroll
            for (int nf=0; nf<8; nf++){
                int n = bn + wn*64 + nf*8 + qp*2;
                float v0 = acc[mf][nf][half*2+0];
                float v1 = acc[mf][nf][half*2+1];
                if (mode==4){
                    int sel = n >> 9;           // 0:q 1:k 2:v
                    int col = n & 511;
                    const float* bs = (sel==0) ? bias0 : (sel==1) ? bias1 : bias2;
                    v0 += bs[col]; v1 += bs[col+1];
                    if (sel < 2){
                        v0 = (v0 > 0.f) ? (v0+1.f) : expf(v0);
                        v1 = (v1 > 0.f) ? (v1+1.f) : expf(v1);
                    }
                    float* Cs = (sel==0) ? C0 : (sel==1) ? C1 : C2;
                    *(float2*)&Cs[(size_t)m*512 + col] = make_float2(v0, v1);
                } else {
                    v0 += bias0[n]; v1 += bias0[n+1];
                    if (mode==3){
                        v0 = fmaxf(v0, 0.f); v1 = fmaxf(v1, 0.f);
                        __nv_bfloat16 h0,l0,h1,l1;
                        bsplit(v0,h0,l0); bsplit(v1,h1,l1);
                        uint32_t hw = ((uint32_t)__bfloat16_as_ushort(h1)<<16) | __bfloat16_as_ushort(h0);
                        uint32_t lw = ((uint32_t)__bfloat16_as_ushort(l1)<<16) | __bfloat16_as_ushort(l0);
                        __nv_bfloat16* p0 = C3 + (size_t)m*3*Np + n;
                        *(uint32_t*)(p0)        = hw;
                        *(uint32_t*)(p0 + Np)   = lw;
                        *(uint32_t*)(p0 + 2*Np) = hw;
                    } else {
                        if (mode==2){
                            float2 rr = *(const float2*)&res[(size_t)m*Np + n];
                            v0 += rr.x; v1 += rr.y;
                        }
                        *(float2*)&C0[(size_t)m*Np + n] = make_float2(v0, v1);
                    }
                }
            }
        }
    }
}

// ---------------- per-chunk K^T V and K sums ----------------
__global__ __launch_bounds__(256) void chunk_sums_kernel(
    const float* __restrict__ Kf, const float* __restrict__ Vf,
    float* __restrict__ ckv, float* __restrict__ cz)
{
    __shared__ float Ks[CHK*DH];
    __shared__ float Vs[CHK*DH];
    int blk = blockIdx.x;
    int c = blk % NC, bh = blk / NC;
    int b = bh / NH, h = bh % NH;
    int t0 = c*CHK;
    int tid = threadIdx.x;
    int lr = tid >> 4;
    int lc = (tid & 15) * 4;
    for (int r = lr; r < CHK; r += 16){
        size_t gi = ((size_t)(b*TT + t0 + r))*DM + h*DH + lc;
        *(float4*)&Ks[r*DH+lc] = *(const float4*)(Kf+gi);
        *(float4*)&Vs[r*DH+lc] = *(const float4*)(Vf+gi);
    }
    __syncthreads();
    int ti = (tid>>4)*4, tj = (tid&15)*4;
    float acc[4][4];
#pragma unroll
    for (int i=0;i<4;i++)
#pragma unroll
        for (int j=0;j<4;j++) acc[i][j]=0.f;
    for (int t=0;t<CHK;t++){
        float4 kv = *(const float4*)&Ks[t*DH+ti];
        float4 vv = *(const float4*)&Vs[t*DH+tj];
        float kk[4]={kv.x,kv.y,kv.z,kv.w}, vf[4]={vv.x,vv.y,vv.z,vv.w};
#pragma unroll
        for (int i=0;i<4;i++)
#pragma unroll
            for (int j=0;j<4;j++) acc[i][j] += kk[i]*vf[j];
    }
    float* outp = ckv + (size_t)blk*DH*DH;
#pragma unroll
    for (int i=0;i<4;i++)
        *(float4*)&outp[(ti+i)*DH + tj] =
            make_float4(acc[i][0],acc[i][1],acc[i][2],acc[i][3]);
    if (tid < DH){
        float zsum = 0.f;
        for (int t=0;t<CHK;t++) zsum += Ks[t*DH+tid];
        cz[(size_t)blk*DH + tid] = zsum;
    }
}

// ---------------- exclusive scan over chunk states ----------------
__global__ __launch_bounds__(256) void scan_kernel(
    const float* __restrict__ ckv, const float* __restrict__ cz,
    float* __restrict__ Sp, float* __restrict__ zp)
{
    int bh = blockIdx.x, tid = threadIdx.x;
    float s[16];
#pragma unroll
    for (int i=0;i<16;i++) s[i]=0.f;
    float z = 0.f;
    for (int c=0;c<NC;c++){
        size_t base = ((size_t)(bh*NC+c))*(DH*DH);
#pragma unroll
        for (int i=0;i<16;i++){
            size_t e = base + (size_t)i*256 + tid;
            Sp[e] = s[i];
            s[i] += ckv[e];
        }
        if (tid < DH){
            size_t ze = (size_t)(bh*NC+c)*DH + tid;
            zp[ze] = z;
            z += cz[ze];
        }
    }
}

// ---------------- intra-chunk attention -> triple bf16 output ----------------
__global__ __launch_bounds__(256) void intra_kernel(
    const float* __restrict__ Qf, const float* __restrict__ Kf,
    const float* __restrict__ Vf, const float* __restrict__ Sp,
    const float* __restrict__ zp, __nv_bfloat16* __restrict__ attn3)
{
    extern __shared__ float smf[];
    float* Qt = smf;
    float* Kt = Qt + 64*STR;
    float* Vs = Kt + 64*STR;
    float* Ss = Vs + 64*STR;
    float* At = Ss + 64*STR;
    float* zs = At + 64*STR;
    float* dn = zs + 64;

    int blk = blockIdx.x;
    int c = blk % NC, bh = blk / NC;
    int b = bh / NH, h = bh % NH;
    int t0 = c*CHK;
    int tid = threadIdx.x;
    int lr = tid >> 4;
    int lc = (tid & 15) * 4;

    for (int r = lr; r < 64; r += 16){
        size_t gi = ((size_t)(b*TT + t0 + r))*DM + h*DH + lc;
        float4 q = *(const float4*)(Qf+gi);
        float4 k = *(const float4*)(Kf+gi);
        float4 v = *(const float4*)(Vf+gi);
        Qt[(lc+0)*STR+r]=q.x; Qt[(lc+1)*STR+r]=q.y; Qt[(lc+2)*STR+r]=q.z; Qt[(lc+3)*STR+r]=q.w;
        Kt[(lc+0)*STR+r]=k.x; Kt[(lc+1)*STR+r]=k.y; Kt[(lc+2)*STR+r]=k.z; Kt[(lc+3)*STR+r]=k.w;
        *(float4*)&Vs[r*STR+lc] = v;
    }
    {
        size_t base = (size_t)blk*(DH*DH);
        for (int e = tid*4; e < DH*DH; e += 1024){
            float4 sv = *(const float4*)(Sp + base + e);
            int d = e >> 6, m = e & 63;
            *(float4*)&Ss[d*STR+m] = sv;
        }
    }
    if (tid < DH) zs[tid] = zp[(size_t)blk*DH + tid];
    __syncthreads();

    int ti = (tid>>4)*4;
    int tj = (tid&15)*4;

    float a[4][4];
#pragma unroll
    for (int i=0;i<4;i++)
#pragma unroll
        for (int j=0;j<4;j++) a[i][j]=0.f;
    for (int d=0; d<64; d++){
        float4 qv = *(const float4*)&Qt[d*STR+ti];
        float4 kv = *(const float4*)&Kt[d*STR+tj];
        float qq[4]={qv.x,qv.y,qv.z,qv.w}, kk[4]={kv.x,kv.y,kv.z,kv.w};
#pragma unroll
        for (int i=0;i<4;i++)
#pragma unroll
            for (int j=0;j<4;j++) a[i][j] += qq[i]*kk[j];
    }
#pragma unroll
    for (int i=0;i<4;i++)
#pragma unroll
        for (int j=0;j<4;j++)
            At[(tj+j)*STR + (ti+i)] = ((tj+j) <= (ti+i)) ? a[i][j] : 0.f;
    __syncthreads();

    if (tid < 64){
        int t = tid;
        float dsum = 0.f;
        for (int j=0;j<64;j++) dsum += At[j*STR + t];
        for (int d=0;d<64;d++) dsum += Qt[d*STR + t]*zs[d];
        dn[t] = fmaxf(dsum, 1e-6f);
    }
    __syncthreads();

    float nacc[4][4];
#pragma unroll
    for (int i=0;i<4;i++)
#pragma unroll
        for (int j=0;j<4;j++) nacc[i][j]=0.f;
    for (int j=0;j<64;j++){
        float4 av = *(const float4*)&At[j*STR+ti];
        float4 vv = *(const float4*)&Vs[j*STR+tj];
        float af[4]={av.x,av.y,av.z,av.w}, vf[4]={vv.x,vv.y,vv.z,vv.w};
#pragma unroll
        for (int i=0;i<4;i++)
#pragma unroll
            for (int m=0;m<4;m++) nacc[i][m] += af[i]*vf[m];
    }
    for (int d=0;d<64;d++){
        float4 qv = *(const float4*)&Qt[d*STR+ti];
        float4 sv = *(const float4*)&Ss[d*STR+tj];
        float qq[4]={qv.x,qv.y,qv.z,qv.w}, sf[4]={sv.x,sv.y,sv.z,sv.w};
#pragma unroll
        for (int i=0;i<4;i++)
#pragma unroll
            for (int m=0;m<4;m++) nacc[i][m] += qq[i]*sf[m];
    }
#pragma unroll
    for (int i=0;i<4;i++){
        float inv = 1.0f / dn[ti+i];
        size_t gm = (size_t)(b*TT + t0 + ti + i);
        __nv_bfloat16* p = attn3 + gm*K3DM + h*DH + tj;
        uint32_t hw[2], lw[2];
#pragma unroll
        for (int q=0;q<2;q++){
            float a0 = nacc[i][2*q]*inv, a1 = nacc[i][2*q+1]*inv;
            __nv_bfloat16 h0,l0,h1,l1;
            bsplit(a0,h0,l0); bsplit(a1,h1,l1);
            hw[q] = ((uint32_t)__bfloat16_as_ushort(h1)<<16) | __bfloat16_as_ushort(h0);
            lw[q] = ((uint32_t)__bfloat16_as_ushort(l1)<<16) | __bfloat16_as_ushort(l0);
        }
        *(uint2*)(p)        = make_uint2(hw[0],hw[1]);
        *(uint2*)(p+DM)     = make_uint2(lw[0],lw[1]);
        *(uint2*)(p+2*DM)   = make_uint2(hw[0],hw[1]);
    }
}

// ---------------- launch ----------------
#define SMEM_INTRA ((5*64*STR + 128) * sizeof(float))

extern "C" void kernel_launch(void* const* d_in, const int* in_sizes, int n_in,
                              void* d_out, int out_size)
{
    (void)in_sizes; (void)n_in; (void)out_size;
    const float* x     = (const float*)d_in[0];
    const float* ln1_g = (const float*)d_in[1];
    const float* ln1_b = (const float*)d_in[2];
    const float* Wq    = (const float*)d_in[3];
    const float* bq    = (const float*)d_in[4];
    const float* Wk    = (const float*)d_in[5];
    const float* bk    = (const float*)d_in[6];
    const float* Wv    = (const float*)d_in[7];
    const float* bv    = (const float*)d_in[8];
    const float* Wo    = (const float*)d_in[9];
    const float* bo    = (const float*)d_in[10];
    const float* ln2_g = (const float*)d_in[11];
    const float* ln2_b = (const float*)d_in[12];
    const float* W1    = (const float*)d_in[13];
    const float* b1    = (const float*)d_in[14];
    const float* W2    = (const float*)d_in[15];
    const float* b2    = (const float*)d_in[16];
    float* out = (float*)d_out;

    static bool attr_done = false;
    if (!attr_done){
        cudaFuncSetAttribute(intra_kernel, cudaFuncAttributeMaxDynamicSharedMemorySize,
                             (int)SMEM_INTRA);
        cudaFuncSetAttribute(mm_kernel, cudaFuncAttributeMaxDynamicSharedMemorySize,
                             SMEM_MM);
        attr_done = true;
    }

    __nv_bfloat16 *h3b,*attn3b,*h23b,*ffn3b,*wqkv3,*wo3,*w13,*w23;
    float *qb,*kb,*vb,*x2b,*ckvb,*czb,*Spb,*zpb;
    cudaGetSymbolAddress((void**)&h3b,   g_h3);
    cudaGetSymbolAddress((void**)&qb,    g_q);
    cudaGetSymbolAddress((void**)&kb,    g_k);
    cudaGetSymbolAddress((void**)&vb,    g_v);
    cudaGetSymbolAddress((void**)&attn3b,g_attn3);
    cudaGetSymbolAddress((void**)&x2b,   g_x2);
    cudaGetSymbolAddress((void**)&h23b,  g_h23);
    cudaGetSymbolAddress((void**)&ffn3b, g_ffn3);
    cudaGetSymbolAddress((void**)&wqkv3, g_wqkv3);
    cudaGetSymbolAddress((void**)&wo3,   g_wo3);
    cudaGetSymbolAddress((void**)&w13,   g_w13);
    cudaGetSymbolAddress((void**)&w23,   g_w23);
    cudaGetSymbolAddress((void**)&ckvb,  g_ckv);
    cudaGetSymbolAddress((void**)&czb,   g_cz);
    cudaGetSymbolAddress((void**)&Spb,   g_Sp);
    cudaGetSymbolAddress((void**)&zpb,   g_zp);

    dim3 wcb(32,8);
    dim3 wc_small(DM/32, DM/64);    // (16, 8)  K=512, N=512
    dim3 wc_w1(DFF/32, DM/64);      // (64, 8)  K=512, N=2048
    dim3 wc_w2(DM/32, DFF/64);      // (16, 32) K=2048, N=512

    wconv_kernel<<<wc_small, wcb>>>(Wq, wqkv3,               DM, DM);
    wconv_kernel<<<wc_small, wcb>>>(Wk, wqkv3 + 512*K3DM,    DM, DM);
    wconv_kernel<<<wc_small, wcb>>>(Wv, wqkv3 + 1024*K3DM,   DM, DM);
    wconv_kernel<<<wc_small, wcb>>>(Wo, wo3, DM, DM);
    wconv_kernel<<<wc_w1, wcb>>>(W1, w13, DM, DFF);
    wconv_kernel<<<wc_w2, wcb>>>(W2, w23, DFF, DM);

    dim3 gQKV(3*DM/TN, MM/TM);      // (12, 32)
    dim3 gDM(DM/TN, MM/TM);         // (4, 32)
    dim3 gFF(DFF/TN, MM/TM);        // (16, 32)

    // sublayer 1
    ln3_kernel<<<MM, 256>>>(x, ln1_g, ln1_b, h3b);
    mm_kernel<<<gQKV, 256, SMEM_MM>>>(h3b, wqkv3, bq, bk, bv, nullptr,
                                      qb, kb, vb, nullptr, DM, K3DM, 4);
    chunk_sums_kernel<<<BH*NC, 256>>>(kb, vb, ckvb, czb);
    scan_kernel<<<BH, 256>>>(ckvb, czb, Spb, zpb);
    intra_kernel<<<BH*NC, 256, SMEM_INTRA>>>(qb, kb, vb, Spb, zpb, attn3b);
    mm_kernel<<<gDM, 256, SMEM_MM>>>(attn3b, wo3, bo, nullptr, nullptr, x,
                                     x2b, nullptr, nullptr, nullptr, DM, K3DM, 2);

    // sublayer 2
    ln3_kernel<<<MM, 256>>>(x2b, ln2_g, ln2_b, h23b);
    mm_kernel<<<gFF, 256, SMEM_MM>>>(h23b, w13, b1, nullptr, nullptr, nullptr,
                                     nullptr, nullptr, nullptr, ffn3b, DFF, K3DM, 3);
    mm_kernel<<<gDM, 256, SMEM_MM>>>(ffn3b, w23, b2, nullptr, nullptr, x2b,
                                     out, nullptr, nullptr, nullptr, DM, K3FF, 2);
}

// round 5
// speedup vs baseline: 2.8182x; 1.0501x over previous
#include <cuda_runtime.h>
#include <cuda_bf16.h>
#include <math.h>
#include <stdint.h>

// ---------------- problem constants ----------------
#define BB   2
#define TT   2048
#define DM   512
#define NH   8
#define DH   64
#define DFF  2048
#define MM   (BB*TT)        // 4096 rows
#define CHK  64
#define NC   (TT/CHK)       // 32
#define BH   (BB*NH)        // 16
#define STR  68
#define K3DM (3*DM)         // 1536
#define K3FF (3*DFF)        // 6144

// ---------------- scratch (device globals) ----------------
__device__ __align__(256) __nv_bfloat16 g_h3   [MM*K3DM];
__device__ __align__(256) float          g_q    [MM*DM];
__device__ __align__(256) float          g_k    [MM*DM];
__device__ __align__(256) float          g_v    [MM*DM];
__device__ __align__(256) __nv_bfloat16 g_attn3[MM*K3DM];
__device__ __align__(256) float          g_x2   [MM*DM];
__device__ __align__(256) __nv_bfloat16 g_h23  [MM*K3DM];
__device__ __align__(256) __nv_bfloat16 g_ffn3 [MM*K3FF];
__device__ __align__(256) __nv_bfloat16 g_wqkv3[3*DM*K3DM];   // rows: [Wq|Wk|Wv]
__device__ __align__(256) __nv_bfloat16 g_wo3  [DM*K3DM];
__device__ __align__(256) __nv_bfloat16 g_w13  [DFF*K3DM];
__device__ __align__(256) __nv_bfloat16 g_w23  [DM*K3FF];
__device__ __align__(256) float g_ckv[BH*NC*DH*DH];
__device__ __align__(256) float g_cz [BH*NC*DH];
__device__ __align__(256) float g_Sp [BH*NC*DH*DH];
__device__ __align__(256) float g_zp [BH*NC*DH];

// ---------------- helpers ----------------
__device__ __forceinline__ uint32_t smem_u32(const void* p){
    uint32_t a;
    asm("{ .reg .u64 t; cvta.to.shared.u64 t, %1; cvt.u32.u64 %0, t; }"
        : "=r"(a) : "l"(p));
    return a;
}
__device__ __forceinline__ void cp16(uint32_t dst, const void* src){
    asm volatile("cp.async.cg.shared.global [%0], [%1], 16;" :: "r"(dst), "l"(src));
}
__device__ __forceinline__ void cp_commit(){
    asm volatile("cp.async.commit_group;");
}
template<int N> __device__ __forceinline__ void cp_wait(){
    asm volatile("cp.async.wait_group %0;" :: "n"(N));
}
__device__ __forceinline__ void bsplit(float v, __nv_bfloat16& h, __nv_bfloat16& l){
    h = __float2bfloat16(v);
    l = __float2bfloat16(v - __bfloat162float(h));
}
__device__ __forceinline__ void mma_bf16(float* d, const uint32_t* a, const uint32_t* b){
    asm volatile(
        "mma.sync.aligned.m16n8k16.row.col.f32.bf16.bf16.f32 "
        "{%0,%1,%2,%3}, {%4,%5,%6,%7}, {%8,%9}, {%0,%1,%2,%3};"
        : "+f"(d[0]), "+f"(d[1]), "+f"(d[2]), "+f"(d[3])
        : "r"(a[0]), "r"(a[1]), "r"(a[2]), "r"(a[3]), "r"(b[0]), "r"(b[1]));
}
__device__ __forceinline__ void ldsm4(uint32_t& r0, uint32_t& r1, uint32_t& r2,
                                      uint32_t& r3, uint32_t addr){
    asm volatile("ldmatrix.sync.aligned.m8n8.x4.shared.b16 {%0,%1,%2,%3}, [%4];"
                 : "=r"(r0), "=r"(r1), "=r"(r2), "=r"(r3) : "r"(addr));
}

// ---------------- layernorm -> triple-bf16 (A-side [hi,lo,hi]) ----------------
__global__ __launch_bounds__(256) void ln3_kernel(
    const float* __restrict__ x, const float* __restrict__ g,
    const float* __restrict__ b, __nv_bfloat16* __restrict__ o3)
{
    int row = blockIdx.x;
    const float* xr = x + (size_t)row*DM;
    int tid = threadIdx.x;
    float v0 = xr[tid], v1 = xr[tid+256];
    float s = v0+v1, s2 = v0*v0+v1*v1;
#pragma unroll
    for (int off=16; off; off>>=1){
        s  += __shfl_xor_sync(0xffffffffu, s,  off);
        s2 += __shfl_xor_sync(0xffffffffu, s2, off);
    }
    __shared__ float rs[8], rs2[8], mu_s, rstd_s;
    if ((tid&31)==0){ rs[tid>>5]=s; rs2[tid>>5]=s2; }
    __syncthreads();
    if (tid==0){
        float a=0.f,c=0.f;
#pragma unroll
        for (int i=0;i<8;i++){ a+=rs[i]; c+=rs2[i]; }
        float mu = a*(1.0f/DM);
        float var = c*(1.0f/DM) - mu*mu;
        mu_s = mu; rstd_s = rsqrtf(var + 1e-5f);
    }
    __syncthreads();
    float mu = mu_s, rstd = rstd_s;
    __nv_bfloat16* orow = o3 + (size_t)row*K3DM;
    {
        float y = (v0-mu)*rstd*g[tid] + b[tid];
        __nv_bfloat16 h,l; bsplit(y,h,l);
        orow[tid] = h; orow[tid+DM] = l; orow[tid+2*DM] = h;
    }
    {
        int c1 = tid+256;
        float y = (v1-mu)*rstd*g[c1] + b[c1];
        __nv_bfloat16 h,l; bsplit(y,h,l);
        orow[c1] = h; orow[c1+DM] = l; orow[c1+2*DM] = h;
    }
}

// -------- fused weight transpose+split: all 6 weights in ONE launch ----------
// block (32,8). 1536 blocks:
//  [0,512):  4 segs of 128 (Wq,Wk,Wv,Wo), Kd=512,Nd=512, nx=16
//  [512,1024): W1  Kd=512,Nd=2048, nx=64
//  [1024,1536): W2 Kd=2048,Nd=512, nx=16
__global__ __launch_bounds__(256) void wconv_all_kernel(
    const float* __restrict__ Wq, const float* __restrict__ Wk,
    const float* __restrict__ Wv, const float* __restrict__ Wo,
    const float* __restrict__ W1, const float* __restrict__ W2,
    __nv_bfloat16* __restrict__ wqkv3, __nv_bfloat16* __restrict__ wo3,
    __nv_bfloat16* __restrict__ w13,   __nv_bfloat16* __restrict__ w23)
{
    int bid = blockIdx.x;
    const float* W; __nv_bfloat16* B3;
    int Kd, Nd, nx, local;
    if (bid < 512){
        int seg = bid >> 7; local = bid & 127; nx = 16; Kd = 512; Nd = 512;
        W  = (seg==0)?Wq:(seg==1)?Wk:(seg==2)?Wv:Wo;
        B3 = (seg==0)?wqkv3:(seg==1)?(wqkv3+512*K3DM):(seg==2)?(wqkv3+1024*K3DM):wo3;
    } else if (bid < 1024){
        local = bid - 512; nx = 64; Kd = 512; Nd = 2048; W = W1; B3 = w13;
    } else {
        local = bid - 1024; nx = 16; Kd = 2048; Nd = 512; W = W2; B3 = w23;
    }
    int n0 = (local % nx)*32, k0 = (local / nx)*64;

    __shared__ float t[64][33];
    int tx = threadIdx.x, ty = threadIdx.y;
#pragma unroll
    for (int i=ty;i<64;i+=8)
        t[i][tx] = W[(size_t)(k0+i)*Nd + n0 + tx];
    __syncthreads();
#pragma unroll
    for (int i=ty;i<32;i+=8){
        float va = t[2*tx][i], vb = t[2*tx+1][i];
        __nv_bfloat16 ha,la,hb,lb;
        bsplit(va,ha,la); bsplit(vb,hb,lb);
        uint32_t hw = ((uint32_t)__bfloat16_as_ushort(hb)<<16) | __bfloat16_as_ushort(ha);
        uint32_t lw = ((uint32_t)__bfloat16_as_ushort(lb)<<16) | __bfloat16_as_ushort(la);
        size_t base = (size_t)(n0+i)*(3*Kd) + k0 + 2*tx;
        *(uint32_t*)&B3[base]        = hw;
        *(uint32_t*)&B3[base+Kd]     = hw;
        *(uint32_t*)&B3[base+2*Kd]   = lw;
    }
}

// ---------------- mma.sync bf16 GEMM, 4-stage cp.async pipeline ----------------
// tile 128x128, 8 warps (warp tile 32x64), K-chunk 64.
// modes: 2 +bias0+res -> C0; 3 relu(+bias0) -> triple bf16 C3;
//        4 qkv split: n<512 -> C0(elu+1,bias0), <1024 -> C1(elu+1,bias1), else C2(bias2)
#define TM 128
#define TN 128
#define RS 72                       // padded smem row (elements)
#define ABY (TM*RS*2)               // 18432 (one operand, one stage)
#define STGB (2*ABY)                // 36864 per stage (A+B)
#define NSTG 4
#define SMEM_MM (NSTG*STGB)         // 147456

__global__ __launch_bounds__(256) void mm_kernel(
    const __nv_bfloat16* __restrict__ Ap, const __nv_bfloat16* __restrict__ Bp,
    const float* __restrict__ bias0, const float* __restrict__ bias1,
    const float* __restrict__ bias2, const float* __restrict__ res,
    float* __restrict__ C0, float* __restrict__ C1, float* __restrict__ C2,
    __nv_bfloat16* __restrict__ C3,
    int Np, int Kp, int mode)
{
    extern __shared__ char smc[];
    uint32_t sb = smem_u32(smc);

    int tid = threadIdx.x;
    int lane = tid & 31, wid = tid >> 5;
    int wm = wid >> 1, wn = wid & 1;
    int g = lane >> 2, qp = lane & 3;
    int bm = blockIdx.y * TM;
    int bn = blockIdx.x * TN;

    const char* Abase = (const char*)(Ap + (size_t)bm*Kp);
    const char* Bbase = (const char*)(Bp + (size_t)bn*Kp);
    const size_t rowb = (size_t)Kp*2;

    int lr_ = tid >> 3, lc_ = (tid & 7)*16;
    auto loadStage = [&](int c, int s){
        uint32_t da = sb + (uint32_t)s*STGB;
        uint32_t db = da + ABY;
        const char* sa = Abase + (size_t)c*128 + (size_t)lr_*rowb + lc_;
        const char* sbp= Bbase + (size_t)c*128 + (size_t)lr_*rowb + lc_;
        uint32_t so = (uint32_t)(lr_*(RS*2) + lc_);
#pragma unroll
        for (int t=0;t<4;t++){
            cp16(da + so + t*32*(RS*2), sa + (size_t)t*32*rowb);
            cp16(db + so + t*32*(RS*2), sbp + (size_t)t*32*rowb);
        }
        cp_commit();
    };

    // per-lane ldmatrix base offsets (within a stage)
    uint32_t a_off[2], b_off[4];
#pragma unroll
    for (int mf=0; mf<2; mf++){
        int arow = wm*32 + mf*16 + (lane & 15);
        a_off[mf] = (uint32_t)(arow*(RS*2) + ((lane & 16) ? 16 : 0));
    }
#pragma unroll
    for (int p=0; p<4; p++){
        int nrow = wn*64 + p*16 + (lane & 7) + ((lane & 16) >> 1);
        b_off[p] = (uint32_t)(nrow*(RS*2) + ((lane & 8) ? 16 : 0)) + ABY;
    }

    float acc[2][8][4];
#pragma unroll
    for (int i=0;i<2;i++)
#pragma unroll
        for (int j=0;j<8;j++)
#pragma unroll
            for (int k=0;k<4;k++) acc[i][j][k]=0.f;

    const int nch = Kp >> 6;
    loadStage(0,0); loadStage(1,1); loadStage(2,2);

    for (int i=0;i<nch;i++){
        cp_wait<NSTG-2>();
        __syncthreads();
        if (i+NSTG-1 < nch) loadStage(i+NSTG-1, (i+NSTG-1) & (NSTG-1));
        else cp_commit();   // keep outstanding-group count invariant
        uint32_t S = sb + (uint32_t)(i & (NSTG-1))*STGB;
#pragma unroll
        for (int ks=0; ks<4; ks++){
            uint32_t koff = (uint32_t)(ks*32);
            uint32_t a[2][4];
            ldsm4(a[0][0],a[0][1],a[0][2],a[0][3], S + a_off[0] + koff);
            ldsm4(a[1][0],a[1][1],a[1][2],a[1][3], S + a_off[1] + koff);
            uint32_t b[8][2];
#pragma unroll
            for (int p=0; p<4; p++)
                ldsm4(b[2*p][0],b[2*p][1],b[2*p+1][0],b[2*p+1][1],
                      S + b_off[p] + koff);
#pragma unroll
            for (int mf=0; mf<2; mf++)
#pragma unroll
                for (int nf=0; nf<8; nf++)
                    mma_bf16(acc[mf][nf], a[mf], b[nf]);
        }
    }

    // ---- epilogue ----
#pragma unroll
    for (int mf=0; mf<2; mf++){
#pragma unroll
        for (int half=0; half<2; half++){
            int m = bm + wm*32 + mf*16 + g + half*8;
#pragma unroll
            for (int nf=0; nf<8; nf++){
                int n = bn + wn*64 + nf*8 + qp*2;
                float v0 = acc[mf][nf][half*2+0];
                float v1 = acc[mf][nf][half*2+1];
                if (mode==4){
                    int sel = n >> 9;           // 0:q 1:k 2:v
                    int col = n & 511;
                    const float* bs = (sel==0) ? bias0 : (sel==1) ? bias1 : bias2;
                    v0 += bs[col]; v1 += bs[col+1];
                    if (sel < 2){
                        v0 = (v0 > 0.f) ? (v0+1.f) : expf(v0);
                        v1 = (v1 > 0.f) ? (v1+1.f) : expf(v1);
                    }
                    float* Cs = (sel==0) ? C0 : (sel==1) ? C1 : C2;
                    *(float2*)&Cs[(size_t)m*512 + col] = make_float2(v0, v1);
                } else {
                    v0 += bias0[n]; v1 += bias0[n+1];
                    if (mode==3){
                        v0 = fmaxf(v0, 0.f); v1 = fmaxf(v1, 0.f);
                        __nv_bfloat16 h0,l0,h1,l1;
                        bsplit(v0,h0,l0); bsplit(v1,h1,l1);
                        uint32_t hw = ((uint32_t)__bfloat16_as_ushort(h1)<<16) | __bfloat16_as_ushort(h0);
                        uint32_t lw = ((uint32_t)__bfloat16_as_ushort(l1)<<16) | __bfloat16_as_ushort(l0);
                        __nv_bfloat16* p0 = C3 + (size_t)m*3*Np + n;
                        *(uint32_t*)(p0)        = hw;
                        *(uint32_t*)(p0 + Np)   = lw;
                        *(uint32_t*)(p0 + 2*Np) = hw;
                    } else {
                        if (mode==2){
                            float2 rr = *(const float2*)&res[(size_t)m*Np + n];
                            v0 += rr.x; v1 += rr.y;
                        }
                        *(float2*)&C0[(size_t)m*Np + n] = make_float2(v0, v1);
                    }
                }
            }
        }
    }
}

// ---------------- per-chunk K^T V and K sums ----------------
__global__ __launch_bounds__(256) void chunk_sums_kernel(
    const float* __restrict__ Kf, const float* __restrict__ Vf,
    float* __restrict__ ckv, float* __restrict__ cz)
{
    __shared__ float Ks[CHK*DH];
    __shared__ float Vs[CHK*DH];
    int blk = blockIdx.x;
    int c = blk % NC, bh = blk / NC;
    int b = bh / NH, h = bh % NH;
    int t0 = c*CHK;
    int tid = threadIdx.x;
    int lr = tid >> 4;
    int lc = (tid & 15) * 4;
    for (int r = lr; r < CHK; r += 16){
        size_t gi = ((size_t)(b*TT + t0 + r))*DM + h*DH + lc;
        *(float4*)&Ks[r*DH+lc] = *(const float4*)(Kf+gi);
        *(float4*)&Vs[r*DH+lc] = *(const float4*)(Vf+gi);
    }
    __syncthreads();
    int ti = (tid>>4)*4, tj = (tid&15)*4;
    float acc[4][4];
#pragma unroll
    for (int i=0;i<4;i++)
#pragma unroll
        for (int j=0;j<4;j++) acc[i][j]=0.f;
    for (int t=0;t<CHK;t++){
        float4 kv = *(const float4*)&Ks[t*DH+ti];
        float4 vv = *(const float4*)&Vs[t*DH+tj];
        float kk[4]={kv.x,kv.y,kv.z,kv.w}, vf[4]={vv.x,vv.y,vv.z,vv.w};
#pragma unroll
        for (int i=0;i<4;i++)
#pragma unroll
            for (int j=0;j<4;j++) acc[i][j] += kk[i]*vf[j];
    }
    float* outp = ckv + (size_t)blk*DH*DH;
#pragma unroll
    for (int i=0;i<4;i++)
        *(float4*)&outp[(ti+i)*DH + tj] =
            make_float4(acc[i][0],acc[i][1],acc[i][2],acc[i][3]);
    if (tid < DH){
        float zsum = 0.f;
        for (int t=0;t<CHK;t++) zsum += Ks[t*DH+tid];
        cz[(size_t)blk*DH + tid] = zsum;
    }
}

// --------- parallel exclusive scan over chunk states: 1 elem / thread ---------
// grid = BH*16 blocks, 256 threads
__global__ __launch_bounds__(256) void scan_kernel(
    const float* __restrict__ ckv, const float* __restrict__ cz,
    float* __restrict__ Sp, float* __restrict__ zp)
{
    int bh = blockIdx.x >> 4;
    int e  = ((blockIdx.x & 15) << 8) + threadIdx.x;   // 0..4095
    size_t base = ((size_t)bh*NC)*(DH*DH) + e;
    float v[NC];
#pragma unroll
    for (int c=0;c<NC;c++) v[c] = ckv[base + (size_t)c*(DH*DH)];
    float s = 0.f;
#pragma unroll
    for (int c=0;c<NC;c++){ Sp[base + (size_t)c*(DH*DH)] = s; s += v[c]; }

    if ((blockIdx.x & 15)==0 && threadIdx.x < DH){
        size_t zb = (size_t)bh*NC*DH + threadIdx.x;
        float zv[NC];
#pragma unroll
        for (int c=0;c<NC;c++) zv[c] = cz[zb + (size_t)c*DH];
        float z = 0.f;
#pragma unroll
        for (int c=0;c<NC;c++){ zp[zb + (size_t)c*DH] = z; z += zv[c]; }
    }
}

// ---------------- intra-chunk attention -> triple bf16 output ----------------
__global__ __launch_bounds__(256) void intra_kernel(
    const float* __restrict__ Qf, const float* __restrict__ Kf,
    const float* __restrict__ Vf, const float* __restrict__ Sp,
    const float* __restrict__ zp, __nv_bfloat16* __restrict__ attn3)
{
    extern __shared__ float smf[];
    float* Qt = smf;
    float* Kt = Qt + 64*STR;
    float* Vs = Kt + 64*STR;
    float* Ss = Vs + 64*STR;
    float* At = Ss + 64*STR;
    float* zs = At + 64*STR;
    float* dn = zs + 64;

    int blk = blockIdx.x;
    int c = blk % NC, bh = blk / NC;
    int b = bh / NH, h = bh % NH;
    int t0 = c*CHK;
    int tid = threadIdx.x;
    int lr = tid >> 4;
    int lc = (tid & 15) * 4;

    for (int r = lr; r < 64; r += 16){
        size_t gi = ((size_t)(b*TT + t0 + r))*DM + h*DH + lc;
        float4 q = *(const float4*)(Qf+gi);
        float4 k = *(const float4*)(Kf+gi);
        float4 v = *(const float4*)(Vf+gi);
        Qt[(lc+0)*STR+r]=q.x; Qt[(lc+1)*STR+r]=q.y; Qt[(lc+2)*STR+r]=q.z; Qt[(lc+3)*STR+r]=q.w;
        Kt[(lc+0)*STR+r]=k.x; Kt[(lc+1)*STR+r]=k.y; Kt[(lc+2)*STR+r]=k.z; Kt[(lc+3)*STR+r]=k.w;
        *(float4*)&Vs[r*STR+lc] = v;
    }
    {
        size_t base = (size_t)blk*(DH*DH);
        for (int e = tid*4; e < DH*DH; e += 1024){
            float4 sv = *(const float4*)(Sp + base + e);
            int d = e >> 6, m = e & 63;
            *(float4*)&Ss[d*STR+m] = sv;
        }
    }
    if (tid < DH) zs[tid] = zp[(size_t)blk*DH + tid];
    __syncthreads();

    int ti = (tid>>4)*4;
    int tj = (tid&15)*4;

    float a[4][4];
#pragma unroll
    for (int i=0;i<4;i++)
#pragma unroll
        for (int j=0;j<4;j++) a[i][j]=0.f;
    for (int d=0; d<64; d++){
        float4 qv = *(const float4*)&Qt[d*STR+ti];
        float4 kv = *(const float4*)&Kt[d*STR+tj];
        float qq[4]={qv.x,qv.y,qv.z,qv.w}, kk[4]={kv.x,kv.y,kv.z,kv.w};
#pragma unroll
        for (int i=0;i<4;i++)
#pragma unroll
            for (int j=0;j<4;j++) a[i][j] += qq[i]*kk[j];
    }
#pragma unroll
    for (int i=0;i<4;i++)
#pragma unroll
        for (int j=0;j<4;j++)
            At[(tj+j)*STR + (ti+i)] = ((tj+j) <= (ti+i)) ? a[i][j] : 0.f;
    __syncthreads();

    if (tid < 64){
        int t = tid;
        float dsum = 0.f;
        for (int j=0;j<64;j++) dsum += At[j*STR + t];
        for (int d=0;d<64;d++) dsum += Qt[d*STR + t]*zs[d];
        dn[t] = fmaxf(dsum, 1e-6f);
    }
    __syncthreads();

    float nacc[4][4];
#pragma unroll
    for (int i=0;i<4;i++)
#pragma unroll
        for (int j=0;j<4;j++) nacc[i][j]=0.f;
    for (int j=0;j<64;j++){
        float4 av = *(const float4*)&At[j*STR+ti];
        float4 vv = *(const float4*)&Vs[j*STR+tj];
        float af[4]={av.x,av.y,av.z,av.w}, vf[4]={vv.x,vv.y,vv.z,vv.w};
#pragma unroll
        for (int i=0;i<4;i++)
#pragma unroll
            for (int m=0;m<4;m++) nacc[i][m] += af[i]*vf[m];
    }
    for (int d=0;d<64;d++){
        float4 qv = *(const float4*)&Qt[d*STR+ti];
        float4 sv = *(const float4*)&Ss[d*STR+tj];
        float qq[4]={qv.x,qv.y,qv.z,qv.w}, sf[4]={sv.x,sv.y,sv.z,sv.w};
#pragma unroll
        for (int i=0;i<4;i++)
#pragma unroll
            for (int m=0;m<4;m++) nacc[i][m] += qq[i]*sf[m];
    }
#pragma unroll
    for (int i=0;i<4;i++){
        float inv = 1.0f / dn[ti+i];
        size_t gm = (size_t)(b*TT + t0 + ti + i);
        __nv_bfloat16* p = attn3 + gm*K3DM + h*DH + tj;
        uint32_t hw[2], lw[2];
#pragma unroll
        for (int q=0;q<2;q++){
            float a0 = nacc[i][2*q]*inv, a1 = nacc[i][2*q+1]*inv;
            __nv_bfloat16 h0,l0,h1,l1;
            bsplit(a0,h0,l0); bsplit(a1,h1,l1);
            hw[q] = ((uint32_t)__bfloat16_as_ushort(h1)<<16) | __bfloat16_as_ushort(h0);
            lw[q] = ((uint32_t)__bfloat16_as_ushort(l1)<<16) | __bfloat16_as_ushort(l0);
        }
        *(uint2*)(p)        = make_uint2(hw[0],hw[1]);
        *(uint2*)(p+DM)     = make_uint2(lw[0],lw[1]);
        *(uint2*)(p+2*DM)   = make_uint2(hw[0],hw[1]);
    }
}

// ---------------- launch ----------------
#define SMEM_INTRA ((5*64*STR + 128) * sizeof(float))

extern "C" void kernel_launch(void* const* d_in, const int* in_sizes, int n_in,
                              void* d_out, int out_size)
{
    (void)in_sizes; (void)n_in; (void)out_size;
    const float* x     = (const float*)d_in[0];
    const float* ln1_g = (const float*)d_in[1];
    const float* ln1_b = (const float*)d_in[2];
    const float* Wq    = (const float*)d_in[3];
    const float* bq    = (const float*)d_in[4];
    const float* Wk    = (const float*)d_in[5];
    const float* bk    = (const float*)d_in[6];
    const float* Wv    = (const float*)d_in[7];
    const float* bv    = (const float*)d_in[8];
    const float* Wo    = (const float*)d_in[9];
    const float* bo    = (const float*)d_in[10];
    const float* ln2_g = (const float*)d_in[11];
    const float* ln2_b = (const float*)d_in[12];
    const float* W1    = (const float*)d_in[13];
    const float* b1    = (const float*)d_in[14];
    const float* W2    = (const float*)d_in[15];
    const float* b2    = (const float*)d_in[16];
    float* out = (float*)d_out;

    static bool attr_done = false;
    if (!attr_done){
        cudaFuncSetAttribute(intra_kernel, cudaFuncAttributeMaxDynamicSharedMemorySize,
                             (int)SMEM_INTRA);
        cudaFuncSetAttribute(mm_kernel, cudaFuncAttributeMaxDynamicSharedMemorySize,
                             SMEM_MM);
        attr_done = true;
    }

    __nv_bfloat16 *h3b,*attn3b,*h23b,*ffn3b,*wqkv3,*wo3,*w13,*w23;
    float *qb,*kb,*vb,*x2b,*ckvb,*czb,*Spb,*zpb;
    cudaGetSymbolAddress((void**)&h3b,   g_h3);
    cudaGetSymbolAddress((void**)&qb,    g_q);
    cudaGetSymbolAddress((void**)&kb,    g_k);
    cudaGetSymbolAddress((void**)&vb,    g_v);
    cudaGetSymbolAddress((void**)&attn3b,g_attn3);
    cudaGetSymbolAddress((void**)&x2b,   g_x2);
    cudaGetSymbolAddress((void**)&h23b,  g_h23);
    cudaGetSymbolAddress((void**)&ffn3b, g_ffn3);
    cudaGetSymbolAddress((void**)&wqkv3, g_wqkv3);
    cudaGetSymbolAddress((void**)&wo3,   g_wo3);
    cudaGetSymbolAddress((void**)&w13,   g_w13);
    cudaGetSymbolAddress((void**)&w23,   g_w23);
    cudaGetSymbolAddress((void**)&ckvb,  g_ckv);
    cudaGetSymbolAddress((void**)&czb,   g_cz);
    cudaGetSymbolAddress((void**)&Spb,   g_Sp);
    cudaGetSymbolAddress((void**)&zpb,   g_zp);

    dim3 wcb(32,8);
    wconv_all_kernel<<<1536, wcb>>>(Wq, Wk, Wv, Wo, W1, W2,
                                    wqkv3, wo3, w13, w23);

    dim3 gQKV(3*DM/TN, MM/TM);      // (12, 32)
    dim3 gDM(DM/TN, MM/TM);         // (4, 32)
    dim3 gFF(DFF/TN, MM/TM);        // (16, 32)

    // sublayer 1
    ln3_kernel<<<MM, 256>>>(x, ln1_g, ln1_b, h3b);
    mm_kernel<<<gQKV, 256, SMEM_MM>>>(h3b, wqkv3, bq, bk, bv, nullptr,
                                      qb, kb, vb, nullptr, DM, K3DM, 4);
    chunk_sums_kernel<<<BH*NC, 256>>>(kb, vb, ckvb, czb);
    scan_kernel<<<BH*16, 256>>>(ckvb, czb, Spb, zpb);
    intra_kernel<<<BH*NC, 256, SMEM_INTRA>>>(qb, kb, vb, Spb, zpb, attn3b);
    mm_kernel<<<gDM, 256, SMEM_MM>>>(attn3b, wo3, bo, nullptr, nullptr, x,
                                     x2b, nullptr, nullptr, nullptr, DM, K3DM, 2);

    // sublayer 2
    ln3_kernel<<<MM, 256>>>(x2b, ln2_g, ln2_b, h23b);
    mm_kernel<<<gFF, 256, SMEM_MM>>>(h23b, w13, b1, nullptr, nullptr, nullptr,
                                     nullptr, nullptr, nullptr, ffn3b, DFF, K3DM, 3);
    mm_kernel<<<gDM, 256, SMEM_MM>>>(ffn3b, w23, b2, nullptr, nullptr, x2b,
                                     out, nullptr, nullptr, nullptr, DM, K3FF, 2);
}

// round 6
// speedup vs baseline: 3.1153x; 1.1054x over previous
#include <cuda_runtime.h>
#include <cuda_bf16.h>
#include <math.h>
#include <stdint.h>

// ---------------- problem constants ----------------
#define BB   2
#define TT   2048
#define DM   512
#define NH   8
#define DH   64
#define DFF  2048
#define MM   (BB*TT)        // 4096 rows
#define CHK  64
#define NC   (TT/CHK)       // 32
#define BH   (BB*NH)        // 16
#define STR  68
#define K3DM (3*DM)         // 1536
#define K3FF (3*DFF)        // 6144

// ---------------- scratch (device globals) ----------------
__device__ __align__(256) __nv_bfloat16 g_h3   [MM*K3DM];
__device__ __align__(256) float          g_q    [MM*DM];
__device__ __align__(256) float          g_k    [MM*DM];
__device__ __align__(256) float          g_v    [MM*DM];
__device__ __align__(256) __nv_bfloat16 g_attn3[MM*K3DM];
__device__ __align__(256) float          g_x2   [MM*DM];
__device__ __align__(256) __nv_bfloat16 g_h23  [MM*K3DM];
__device__ __align__(256) __nv_bfloat16 g_ffn3 [MM*K3FF];
__device__ __align__(256) __nv_bfloat16 g_wqkv3[3*DM*K3DM];   // rows: [Wq|Wk|Wv]
__device__ __align__(256) __nv_bfloat16 g_wo3  [DM*K3DM];
__device__ __align__(256) __nv_bfloat16 g_w13  [DFF*K3DM];
__device__ __align__(256) __nv_bfloat16 g_w23  [DM*K3FF];
__device__ __align__(256) float g_ckv[BH*NC*DH*DH];
__device__ __align__(256) float g_cz [BH*NC*DH];
__device__ __align__(256) float g_Sp [BH*NC*DH*DH];
__device__ __align__(256) float g_zp [BH*NC*DH];

// ---------------- helpers ----------------
__device__ __forceinline__ uint32_t smem_u32(const void* p){
    uint32_t a;
    asm("{ .reg .u64 t; cvta.to.shared.u64 t, %1; cvt.u32.u64 %0, t; }"
        : "=r"(a) : "l"(p));
    return a;
}
__device__ __forceinline__ void cp16(uint32_t dst, const void* src){
    asm volatile("cp.async.cg.shared.global [%0], [%1], 16;" :: "r"(dst), "l"(src));
}
__device__ __forceinline__ void cp_commit(){
    asm volatile("cp.async.commit_group;");
}
template<int N> __device__ __forceinline__ void cp_wait(){
    asm volatile("cp.async.wait_group %0;" :: "n"(N));
}
__device__ __forceinline__ void bsplit(float v, __nv_bfloat16& h, __nv_bfloat16& l){
    h = __float2bfloat16(v);
    l = __float2bfloat16(v - __bfloat162float(h));
}
__device__ __forceinline__ void mma_bf16(float* d, const uint32_t* a, const uint32_t* b){
    asm volatile(
        "mma.sync.aligned.m16n8k16.row.col.f32.bf16.bf16.f32 "
        "{%0,%1,%2,%3}, {%4,%5,%6,%7}, {%8,%9}, {%0,%1,%2,%3};"
        : "+f"(d[0]), "+f"(d[1]), "+f"(d[2]), "+f"(d[3])
        : "r"(a[0]), "r"(a[1]), "r"(a[2]), "r"(a[3]), "r"(b[0]), "r"(b[1]));
}
__device__ __forceinline__ void ldsm4(uint32_t& r0, uint32_t& r1, uint32_t& r2,
                                      uint32_t& r3, uint32_t addr){
    asm volatile("ldmatrix.sync.aligned.m8n8.x4.shared.b16 {%0,%1,%2,%3}, [%4];"
                 : "=r"(r0), "=r"(r1), "=r"(r2), "=r"(r3) : "r"(addr));
}

// ---------------- layernorm -> triple-bf16 (A-side [hi,lo,hi]) ----------------
__global__ __launch_bounds__(256) void ln3_kernel(
    const float* __restrict__ x, const float* __restrict__ g,
    const float* __restrict__ b, __nv_bfloat16* __restrict__ o3)
{
    int row = blockIdx.x;
    const float* xr = x + (size_t)row*DM;
    int tid = threadIdx.x;
    float v0 = xr[tid], v1 = xr[tid+256];
    float s = v0+v1, s2 = v0*v0+v1*v1;
#pragma unroll
    for (int off=16; off; off>>=1){
        s  += __shfl_xor_sync(0xffffffffu, s,  off);
        s2 += __shfl_xor_sync(0xffffffffu, s2, off);
    }
    __shared__ float rs[8], rs2[8], mu_s, rstd_s;
    if ((tid&31)==0){ rs[tid>>5]=s; rs2[tid>>5]=s2; }
    __syncthreads();
    if (tid==0){
        float a=0.f,c=0.f;
#pragma unroll
        for (int i=0;i<8;i++){ a+=rs[i]; c+=rs2[i]; }
        float mu = a*(1.0f/DM);
        float var = c*(1.0f/DM) - mu*mu;
        mu_s = mu; rstd_s = rsqrtf(var + 1e-5f);
    }
    __syncthreads();
    float mu = mu_s, rstd = rstd_s;
    __nv_bfloat16* orow = o3 + (size_t)row*K3DM;
    {
        float y = (v0-mu)*rstd*g[tid] + b[tid];
        __nv_bfloat16 h,l; bsplit(y,h,l);
        orow[tid] = h; orow[tid+DM] = l; orow[tid+2*DM] = h;
    }
    {
        int c1 = tid+256;
        float y = (v1-mu)*rstd*g[c1] + b[c1];
        __nv_bfloat16 h,l; bsplit(y,h,l);
        orow[c1] = h; orow[c1+DM] = l; orow[c1+2*DM] = h;
    }
}

// -------- fused weight transpose+split: all 6 weights in ONE launch ----------
__global__ __launch_bounds__(256) void wconv_all_kernel(
    const float* __restrict__ Wq, const float* __restrict__ Wk,
    const float* __restrict__ Wv, const float* __restrict__ Wo,
    const float* __restrict__ W1, const float* __restrict__ W2,
    __nv_bfloat16* __restrict__ wqkv3, __nv_bfloat16* __restrict__ wo3,
    __nv_bfloat16* __restrict__ w13,   __nv_bfloat16* __restrict__ w23)
{
    int bid = blockIdx.x;
    const float* W; __nv_bfloat16* B3;
    int Kd, Nd, nx, local;
    if (bid < 512){
        int seg = bid >> 7; local = bid & 127; nx = 16; Kd = 512; Nd = 512;
        W  = (seg==0)?Wq:(seg==1)?Wk:(seg==2)?Wv:Wo;
        B3 = (seg==0)?wqkv3:(seg==1)?(wqkv3+512*K3DM):(seg==2)?(wqkv3+1024*K3DM):wo3;
    } else if (bid < 1024){
        local = bid - 512; nx = 64; Kd = 512; Nd = 2048; W = W1; B3 = w13;
    } else {
        local = bid - 1024; nx = 16; Kd = 2048; Nd = 512; W = W2; B3 = w23;
    }
    int n0 = (local % nx)*32, k0 = (local / nx)*64;

    __shared__ float t[64][33];
    int tx = threadIdx.x, ty = threadIdx.y;
#pragma unroll
    for (int i=ty;i<64;i+=8)
        t[i][tx] = W[(size_t)(k0+i)*Nd + n0 + tx];
    __syncthreads();
#pragma unroll
    for (int i=ty;i<32;i+=8){
        float va = t[2*tx][i], vb = t[2*tx+1][i];
        __nv_bfloat16 ha,la,hb,lb;
        bsplit(va,ha,la); bsplit(vb,hb,lb);
        uint32_t hw = ((uint32_t)__bfloat16_as_ushort(hb)<<16) | __bfloat16_as_ushort(ha);
        uint32_t lw = ((uint32_t)__bfloat16_as_ushort(lb)<<16) | __bfloat16_as_ushort(la);
        size_t base = (size_t)(n0+i)*(3*Kd) + k0 + 2*tx;
        *(uint32_t*)&B3[base]        = hw;
        *(uint32_t*)&B3[base+Kd]     = hw;
        *(uint32_t*)&B3[base+2*Kd]   = lw;
    }
}

// ---------------- mma.sync bf16 GEMM, 3-stage pipeline, 2 CTAs/SM ----------------
// tile 128x128, 8 warps (warp tile 32x64), K-chunk 64.
// modes: 2 +bias0+res -> C0; 3 relu(+bias0) -> triple bf16 C3;
//        4 qkv split: n<512 -> C0(elu+1,bias0), <1024 -> C1(elu+1,bias1), else C2(bias2)
#define TM 128
#define TN 128
#define RS 72                       // padded smem row (elements)
#define ABY (TM*RS*2)               // 18432 (one operand, one stage)
#define STGB (2*ABY)                // 36864 per stage (A+B)
#define NSTG 3
#define SMEM_MM (NSTG*STGB)         // 110592 -> two CTAs fit per SM

__global__ __launch_bounds__(256, 2) void mm_kernel(
    const __nv_bfloat16* __restrict__ Ap, const __nv_bfloat16* __restrict__ Bp,
    const float* __restrict__ bias0, const float* __restrict__ bias1,
    const float* __restrict__ bias2, const float* __restrict__ res,
    float* __restrict__ C0, float* __restrict__ C1, float* __restrict__ C2,
    __nv_bfloat16* __restrict__ C3,
    int Np, int Kp, int mode)
{
    extern __shared__ char smc[];
    uint32_t sb = smem_u32(smc);

    int tid = threadIdx.x;
    int lane = tid & 31, wid = tid >> 5;
    int wm = wid >> 1, wn = wid & 1;
    int g = lane >> 2, qp = lane & 3;
    int bm = blockIdx.y * TM;
    int bn = blockIdx.x * TN;

    const char* Abase = (const char*)(Ap + (size_t)bm*Kp);
    const char* Bbase = (const char*)(Bp + (size_t)bn*Kp);
    const size_t rowb = (size_t)Kp*2;

    int lr_ = tid >> 3, lc_ = (tid & 7)*16;
    auto loadStage = [&](int c, int s){
        uint32_t da = sb + (uint32_t)s*STGB;
        uint32_t db = da + ABY;
        const char* sa = Abase + (size_t)c*128 + (size_t)lr_*rowb + lc_;
        const char* sbp= Bbase + (size_t)c*128 + (size_t)lr_*rowb + lc_;
        uint32_t so = (uint32_t)(lr_*(RS*2) + lc_);
#pragma unroll
        for (int t=0;t<4;t++){
            cp16(da + so + t*32*(RS*2), sa + (size_t)t*32*rowb);
            cp16(db + so + t*32*(RS*2), sbp + (size_t)t*32*rowb);
        }
        cp_commit();
    };

    // per-lane ldmatrix base offsets (within a stage)
    uint32_t a_off[2], b_off[4];
#pragma unroll
    for (int mf=0; mf<2; mf++){
        int arow = wm*32 + mf*16 + (lane & 15);
        a_off[mf] = (uint32_t)(arow*(RS*2) + ((lane & 16) ? 16 : 0));
    }
#pragma unroll
    for (int p=0; p<4; p++){
        int nrow = wn*64 + p*16 + (lane & 7) + ((lane & 16) >> 1);
        b_off[p] = (uint32_t)(nrow*(RS*2) + ((lane & 8) ? 16 : 0)) + ABY;
    }

    float acc[2][8][4];
#pragma unroll
    for (int i=0;i<2;i++)
#pragma unroll
        for (int j=0;j<8;j++)
#pragma unroll
            for (int k=0;k<4;k++) acc[i][j][k]=0.f;

    const int nch = Kp >> 6;
    loadStage(0,0); loadStage(1,1);

    int cur = 0;            // stage of chunk i
    int nxt = 2;            // stage for chunk i+2
    for (int i=0;i<nch;i++){
        cp_wait<NSTG-2>();
        __syncthreads();
        if (i+2 < nch) loadStage(i+2, nxt);
        else cp_commit();   // keep outstanding-group count invariant
        uint32_t S = sb + (uint32_t)cur*STGB;
#pragma unroll
        for (int ks=0; ks<4; ks++){
            uint32_t koff = (uint32_t)(ks*32);
            uint32_t a[2][4];
            ldsm4(a[0][0],a[0][1],a[0][2],a[0][3], S + a_off[0] + koff);
            ldsm4(a[1][0],a[1][1],a[1][2],a[1][3], S + a_off[1] + koff);
            uint32_t b[8][2];
#pragma unroll
            for (int p=0; p<4; p++)
                ldsm4(b[2*p][0],b[2*p][1],b[2*p+1][0],b[2*p+1][1],
                      S + b_off[p] + koff);
#pragma unroll
            for (int mf=0; mf<2; mf++)
#pragma unroll
                for (int nf=0; nf<8; nf++)
                    mma_bf16(acc[mf][nf], a[mf], b[nf]);
        }
        cur = (cur==NSTG-1) ? 0 : cur+1;
        nxt = (nxt==NSTG-1) ? 0 : nxt+1;
    }

    // ---- epilogue ----
#pragma unroll
    for (int mf=0; mf<2; mf++){
#pragma unroll
        for (int half=0; half<2; half++){
            int m = bm + wm*32 + mf*16 + g + half*8;
#pragma unroll
            for (int nf=0; nf<8; nf++){
                int n = bn + wn*64 + nf*8 + qp*2;
                float v0 = acc[mf][nf][half*2+0];
                float v1 = acc[mf][nf][half*2+1];
                if (mode==4){
                    int sel = n >> 9;           // 0:q 1:k 2:v
                    int col = n & 511;
                    const float* bs = (sel==0) ? bias0 : (sel==1) ? bias1 : bias2;
                    v0 += bs[col]; v1 += bs[col+1];
                    if (sel < 2){
                        v0 = (v0 > 0.f) ? (v0+1.f) : expf(v0);
                        v1 = (v1 > 0.f) ? (v1+1.f) : expf(v1);
                    }
                    float* Cs = (sel==0) ? C0 : (sel==1) ? C1 : C2;
                    *(float2*)&Cs[(size_t)m*512 + col] = make_float2(v0, v1);
                } else {
                    v0 += bias0[n]; v1 += bias0[n+1];
                    if (mode==3){
                        v0 = fmaxf(v0, 0.f); v1 = fmaxf(v1, 0.f);
                        __nv_bfloat16 h0,l0,h1,l1;
                        bsplit(v0,h0,l0); bsplit(v1,h1,l1);
                        uint32_t hw = ((uint32_t)__bfloat16_as_ushort(h1)<<16) | __bfloat16_as_ushort(h0);
                        uint32_t lw = ((uint32_t)__bfloat16_as_ushort(l1)<<16) | __bfloat16_as_ushort(l0);
                        __nv_bfloat16* p0 = C3 + (size_t)m*3*Np + n;
                        *(uint32_t*)(p0)        = hw;
                        *(uint32_t*)(p0 + Np)   = lw;
                        *(uint32_t*)(p0 + 2*Np) = hw;
                    } else {
                        if (mode==2){
                            float2 rr = *(const float2*)&res[(size_t)m*Np + n];
                            v0 += rr.x; v1 += rr.y;
                        }
                        *(float2*)&C0[(size_t)m*Np + n] = make_float2(v0, v1);
                    }
                }
            }
        }
    }
}

// ---------------- per-chunk K^T V and K sums ----------------
__global__ __launch_bounds__(256) void chunk_sums_kernel(
    const float* __restrict__ Kf, const float* __restrict__ Vf,
    float* __restrict__ ckv, float* __restrict__ cz)
{
    __shared__ float Ks[CHK*DH];
    __shared__ float Vs[CHK*DH];
    int blk = blockIdx.x;
    int c = blk % NC, bh = blk / NC;
    int b = bh / NH, h = bh % NH;
    int t0 = c*CHK;
    int tid = threadIdx.x;
    int lr = tid >> 4;
    int lc = (tid & 15) * 4;
    for (int r = lr; r < CHK; r += 16){
        size_t gi = ((size_t)(b*TT + t0 + r))*DM + h*DH + lc;
        *(float4*)&Ks[r*DH+lc] = *(const float4*)(Kf+gi);
        *(float4*)&Vs[r*DH+lc] = *(const float4*)(Vf+gi);
    }
    __syncthreads();
    int ti = (tid>>4)*4, tj = (tid&15)*4;
    float acc[4][4];
#pragma unroll
    for (int i=0;i<4;i++)
#pragma unroll
        for (int j=0;j<4;j++) acc[i][j]=0.f;
    for (int t=0;t<CHK;t++){
        float4 kv = *(const float4*)&Ks[t*DH+ti];
        float4 vv = *(const float4*)&Vs[t*DH+tj];
        float kk[4]={kv.x,kv.y,kv.z,kv.w}, vf[4]={vv.x,vv.y,vv.z,vv.w};
#pragma unroll
        for (int i=0;i<4;i++)
#pragma unroll
            for (int j=0;j<4;j++) acc[i][j] += kk[i]*vf[j];
    }
    float* outp = ckv + (size_t)blk*DH*DH;
#pragma unroll
    for (int i=0;i<4;i++)
        *(float4*)&outp[(ti+i)*DH + tj] =
            make_float4(acc[i][0],acc[i][1],acc[i][2],acc[i][3]);
    if (tid < DH){
        float zsum = 0.f;
        for (int t=0;t<CHK;t++) zsum += Ks[t*DH+tid];
        cz[(size_t)blk*DH + tid] = zsum;
    }
}

// --------- parallel exclusive scan over chunk states: 1 elem / thread ---------
__global__ __launch_bounds__(256) void scan_kernel(
    const float* __restrict__ ckv, const float* __restrict__ cz,
    float* __restrict__ Sp, float* __restrict__ zp)
{
    int bh = blockIdx.x >> 4;
    int e  = ((blockIdx.x & 15) << 8) + threadIdx.x;   // 0..4095
    size_t base = ((size_t)bh*NC)*(DH*DH) + e;
    float v[NC];
#pragma unroll
    for (int c=0;c<NC;c++) v[c] = ckv[base + (size_t)c*(DH*DH)];
    float s = 0.f;
#pragma unroll
    for (int c=0;c<NC;c++){ Sp[base + (size_t)c*(DH*DH)] = s; s += v[c]; }

    if ((blockIdx.x & 15)==0 && threadIdx.x < DH){
        size_t zb = (size_t)bh*NC*DH + threadIdx.x;
        float zv[NC];
#pragma unroll
        for (int c=0;c<NC;c++) zv[c] = cz[zb + (size_t)c*DH];
        float z = 0.f;
#pragma unroll
        for (int c=0;c<NC;c++){ zp[zb + (size_t)c*DH] = z; z += zv[c]; }
    }
}

// ---------------- intra-chunk attention -> triple bf16 output ----------------
__global__ __launch_bounds__(256) void intra_kernel(
    const float* __restrict__ Qf, const float* __restrict__ Kf,
    const float* __restrict__ Vf, const float* __restrict__ Sp,
    const float* __restrict__ zp, __nv_bfloat16* __restrict__ attn3)
{
    extern __shared__ float smf[];
    float* Qt = smf;
    float* Kt = Qt + 64*STR;
    float* Vs = Kt + 64*STR;
    float* Ss = Vs + 64*STR;
    float* At = Ss + 64*STR;
    float* zs = At + 64*STR;
    float* dn = zs + 64;

    int blk = blockIdx.x;
    int c = blk % NC, bh = blk / NC;
    int b = bh / NH, h = bh % NH;
    int t0 = c*CHK;
    int tid = threadIdx.x;
    int lr = tid >> 4;
    int lc = (tid & 15) * 4;

    for (int r = lr; r < 64; r += 16){
        size_t gi = ((size_t)(b*TT + t0 + r))*DM + h*DH + lc;
        float4 q = *(const float4*)(Qf+gi);
        float4 k = *(const float4*)(Kf+gi);
        float4 v = *(const float4*)(Vf+gi);
        Qt[(lc+0)*STR+r]=q.x; Qt[(lc+1)*STR+r]=q.y; Qt[(lc+2)*STR+r]=q.z; Qt[(lc+3)*STR+r]=q.w;
        Kt[(lc+0)*STR+r]=k.x; Kt[(lc+1)*STR+r]=k.y; Kt[(lc+2)*STR+r]=k.z; Kt[(lc+3)*STR+r]=k.w;
        *(float4*)&Vs[r*STR+lc] = v;
    }
    {
        size_t base = (size_t)blk*(DH*DH);
        for (int e = tid*4; e < DH*DH; e += 1024){
            float4 sv = *(const float4*)(Sp + base + e);
            int d = e >> 6, m = e & 63;
            *(float4*)&Ss[d*STR+m] = sv;
        }
    }
    if (tid < DH) zs[tid] = zp[(size_t)blk*DH + tid];
    __syncthreads();

    int ti = (tid>>4)*4;
    int tj = (tid&15)*4;

    float a[4][4];
#pragma unroll
    for (int i=0;i<4;i++)
#pragma unroll
        for (int j=0;j<4;j++) a[i][j]=0.f;
    for (int d=0; d<64; d++){
        float4 qv = *(const float4*)&Qt[d*STR+ti];
        float4 kv = *(const float4*)&Kt[d*STR+tj];
        float qq[4]={qv.x,qv.y,qv.z,qv.w}, kk[4]={kv.x,kv.y,kv.z,kv.w};
#pragma unroll
        for (int i=0;i<4;i++)
#pragma unroll
            for (int j=0;j<4;j++) a[i][j] += qq[i]*kk[j];
    }
#pragma unroll
    for (int i=0;i<4;i++)
#pragma unroll
        for (int j=0;j<4;j++)
            At[(tj+j)*STR + (ti+i)] = ((tj+j) <= (ti+i)) ? a[i][j] : 0.f;
    __syncthreads();

    if (tid < 64){
        int t = tid;
        float dsum = 0.f;
        for (int j=0;j<64;j++) dsum += At[j*STR + t];
        for (int d=0;d<64;d++) dsum += Qt[d*STR + t]*zs[d];
        dn[t] = fmaxf(dsum, 1e-6f);
    }
    __syncthreads();

    float nacc[4][4];
#pragma unroll
    for (int i=0;i<4;i++)
#pragma unroll
        for (int j=0;j<4;j++) nacc[i][j]=0.f;
    for (int j=0;j<64;j++){
        float4 av = *(const float4*)&At[j*STR+ti];
        float4 vv = *(const float4*)&Vs[j*STR+tj];
        float af[4]={av.x,av.y,av.z,av.w}, vf[4]={vv.x,vv.y,vv.z,vv.w};
#pragma unroll
        for (int i=0;i<4;i++)
#pragma unroll
            for (int m=0;m<4;m++) nacc[i][m] += af[i]*vf[m];
    }
    for (int d=0;d<64;d++){
        float4 qv = *(const float4*)&Qt[d*STR+ti];
        float4 sv = *(const float4*)&Ss[d*STR+tj];
        float qq[4]={qv.x,qv.y,qv.z,qv.w}, sf[4]={sv.x,sv.y,sv.z,sv.w};
#pragma unroll
        for (int i=0;i<4;i++)
#pragma unroll
            for (int m=0;m<4;m++) nacc[i][m] += qq[i]*sf[m];
    }
#pragma unroll
    for (int i=0;i<4;i++){
        float inv = 1.0f / dn[ti+i];
        size_t gm = (size_t)(b*TT + t0 + ti + i);
        __nv_bfloat16* p = attn3 + gm*K3DM + h*DH + tj;
        uint32_t hw[2], lw[2];
#pragma unroll
        for (int q=0;q<2;q++){
            float a0 = nacc[i][2*q]*inv, a1 = nacc[i][2*q+1]*inv;
            __nv_bfloat16 h0,l0,h1,l1;
            bsplit(a0,h0,l0); bsplit(a1,h1,l1);
            hw[q] = ((uint32_t)__bfloat16_as_ushort(h1)<<16) | __bfloat16_as_ushort(h0);
            lw[q] = ((uint32_t)__bfloat16_as_ushort(l1)<<16) | __bfloat16_as_ushort(l0);
        }
        *(uint2*)(p)        = make_uint2(hw[0],hw[1]);
        *(uint2*)(p+DM)     = make_uint2(lw[0],lw[1]);
        *(uint2*)(p+2*DM)   = make_uint2(hw[0],hw[1]);
    }
}

// ---------------- launch ----------------
#define SMEM_INTRA ((5*64*STR + 128) * sizeof(float))

extern "C" void kernel_launch(void* const* d_in, const int* in_sizes, int n_in,
                              void* d_out, int out_size)
{
    (void)in_sizes; (void)n_in; (void)out_size;
    const float* x     = (const float*)d_in[0];
    const float* ln1_g = (const float*)d_in[1];
    const float* ln1_b = (const float*)d_in[2];
    const float* Wq    = (const float*)d_in[3];
    const float* bq    = (const float*)d_in[4];
    const float* Wk    = (const float*)d_in[5];
    const float* bk    = (const float*)d_in[6];
    const float* Wv    = (const float*)d_in[7];
    const float* bv    = (const float*)d_in[8];
    const float* Wo    = (const float*)d_in[9];
    const float* bo    = (const float*)d_in[10];
    const float* ln2_g = (const float*)d_in[11];
    const float* ln2_b = (const float*)d_in[12];
    const float* W1    = (const float*)d_in[13];
    const float* b1    = (const float*)d_in[14];
    const float* W2    = (const float*)d_in[15];
    const float* b2    = (const float*)d_in[16];
    float* out = (float*)d_out;

    static bool attr_done = false;
    if (!attr_done){
        cudaFuncSetAttribute(intra_kernel, cudaFuncAttributeMaxDynamicSharedMemorySize,
                             (int)SMEM_INTRA);
        cudaFuncSetAttribute(mm_kernel, cudaFuncAttributeMaxDynamicSharedMemorySize,
                             SMEM_MM);
        attr_done = true;
    }

    __nv_bfloat16 *h3b,*attn3b,*h23b,*ffn3b,*wqkv3,*wo3,*w13,*w23;
    float *qb,*kb,*vb,*x2b,*ckvb,*czb,*Spb,*zpb;
    cudaGetSymbolAddress((void**)&h3b,   g_h3);
    cudaGetSymbolAddress((void**)&qb,    g_q);
    cudaGetSymbolAddress((void**)&kb,    g_k);
    cudaGetSymbolAddress((void**)&vb,    g_v);
    cudaGetSymbolAddress((void**)&attn3b,g_attn3);
    cudaGetSymbolAddress((void**)&x2b,   g_x2);
    cudaGetSymbolAddress((void**)&h23b,  g_h23);
    cudaGetSymbolAddress((void**)&ffn3b, g_ffn3);
    cudaGetSymbolAddress((void**)&wqkv3, g_wqkv3);
    cudaGetSymbolAddress((void**)&wo3,   g_wo3);
    cudaGetSymbolAddress((void**)&w13,   g_w13);
    cudaGetSymbolAddress((void**)&w23,   g_w23);
    cudaGetSymbolAddress((void**)&ckvb,  g_ckv);
    cudaGetSymbolAddress((void**)&czb,   g_cz);
    cudaGetSymbolAddress((void**)&Spb,   g_Sp);
    cudaGetSymbolAddress((void**)&zpb,   g_zp);

    dim3 wcb(32,8);
    wconv_all_kernel<<<1536, wcb>>>(Wq, Wk, Wv, Wo, W1, W2,
                                    wqkv3, wo3, w13, w23);

    dim3 gQKV(3*DM/TN, MM/TM);      // (12, 32)
    dim3 gDM(DM/TN, MM/TM);         // (4, 32)
    dim3 gFF(DFF/TN, MM/TM);        // (16, 32)

    // sublayer 1
    ln3_kernel<<<MM, 256>>>(x, ln1_g, ln1_b, h3b);
    mm_kernel<<<gQKV, 256, SMEM_MM>>>(h3b, wqkv3, bq, bk, bv, nullptr,
                                      qb, kb, vb, nullptr, DM, K3DM, 4);
    chunk_sums_kernel<<<BH*NC, 256>>>(kb, vb, ckvb, czb);
    scan_kernel<<<BH*16, 256>>>(ckvb, czb, Spb, zpb);
    intra_kernel<<<BH*NC, 256, SMEM_INTRA>>>(qb, kb, vb, Spb, zpb, attn3b);
    mm_kernel<<<gDM, 256, SMEM_MM>>>(attn3b, wo3, bo, nullptr, nullptr, x,
                                     x2b, nullptr, nullptr, nullptr, DM, K3DM, 2);

    // sublayer 2
    ln3_kernel<<<MM, 256>>>(x2b, ln2_g, ln2_b, h23b);
    mm_kernel<<<gFF, 256, SMEM_MM>>>(h23b, w13, b1, nullptr, nullptr, nullptr,
                                     nullptr, nullptr, nullptr, ffn3b, DFF, K3DM, 3);
    mm_kernel<<<gDM, 256, SMEM_MM>>>(ffn3b, w23, b2, nullptr, nullptr, x2b,
                                     out, nullptr, nullptr, nullptr, DM, K3FF, 2);
}